// round 1
// baseline (speedup 1.0000x reference)
#include <cuda_runtime.h>
#include <math_constants.h>

// Problem constants
#define BB 2
#define NN 2048
#define MM 512
#define GG 27
#define CIG 41
#define CAGG 32
#define CPOST 128
#define GC (GG*CAGG)      // 864
#define BM (BB*MM)        // 1024
#define NCENT (BM*GG)     // 27648
#define VPITCH 48

// Scratch (device globals; no allocation allowed)
__device__ __align__(16) float g_feats[BB*NN*32];       // 512 KB
__device__ __align__(16) float g_vec[NCENT*VPITCH];     // 5.3 MB
__device__ __align__(16) float g_x[BM*GC];              // 3.5 MB

// ---------------------------------------------------------------------------
// K0: channel reduction  (BN*128) -> (BN*32):  sum of 4 chunks of 32
// ---------------------------------------------------------------------------
__global__ void k_reduce(const float* __restrict__ sf) {
    int t = blockIdx.x * 256 + threadIdx.x;
    if (t >= BB*NN*32) return;
    int n = t >> 5, c = t & 31;
    const float* p = sf + n*128 + c;
    g_feats[t] = p[0] + p[32] + p[64] + p[96];
}

// Branchless insert of (d,i) into sorted triple d0<=d1<=d2
__device__ __forceinline__ void ins3(float d, int i,
        float& d0, int& i0, float& d1, int& i1, float& d2, int& i2) {
    bool c2 = d < d2, c1 = d < d1, c0 = d < d0;
    d2 = c1 ? d1 : (c2 ? d : d2);  i2 = c1 ? i1 : (c2 ? i : i2);
    d1 = c0 ? d0 : (c1 ? d : d1);  i1 = c0 ? i0 : (c1 ? i : i1);
    d0 = c0 ? d  : d0;             i0 = c0 ? i  : i0;
}

// ---------------------------------------------------------------------------
// K1: per-center 3-NN (cube-filtered) + weighted interp + local xyz
// One warp per center. Support points of the batch cached in SMEM.
// ---------------------------------------------------------------------------
__global__ __launch_bounds__(256) void k_interp(
        const float* __restrict__ sxyz, const float* __restrict__ nxyz) {
    __shared__ float4 spt[NN];   // 32 KB
    const int tid  = threadIdx.x;
    const int cid0 = blockIdx.x * 8;
    const int batch = cid0 / (MM*GG);

    // cooperative load of this batch's support points (xyz -> float4)
    {
        const float* sx = sxyz + batch*NN*3;
        float* sptf = (float*)spt;
        for (int t = tid; t < NN*3; t += 256) {
            int pt = t / 3, cc = t - pt*3;
            sptf[pt*4 + cc] = sx[t];
        }
    }
    __syncthreads();

    const int warp = tid >> 5, lane = tid & 31;
    const int cid = cid0 + warp;
    const int m = cid / GG, g = cid - m*GG;

    // grid offsets: (i + 0.5f) * 1.6f - 2.4f  (exact fp32 sequence of reference)
    const int ixg = g / 9;
    const int iyg = (g - ixg*9) / 3;
    const int izg = g - ixg*9 - iyg*3;
    const float offx = __fadd_rn(__fmul_rn((float)ixg + 0.5f, 1.6f), -2.4f);
    const float offy = __fadd_rn(__fmul_rn((float)iyg + 0.5f, 1.6f), -2.4f);
    const float offz = __fadd_rn(__fmul_rn((float)izg + 0.5f, 1.6f), -2.4f);
    const float cx = nxyz[m*3+0] + offx;
    const float cy = nxyz[m*3+1] + offy;
    const float cz = nxyz[m*3+2] + offz;

    const float INF = CUDART_INF_F;
    float d0 = INF, d1 = INF, d2v = INF;
    int   i0 = -1,  i1 = -1,  i2 = -1;

    #pragma unroll 4
    for (int t = lane; t < NN; t += 32) {
        float4 p = spt[t];
        float dx = cx - p.x, dy = cy - p.y, dz = cz - p.z;
        float dsq = fmaf(dx, dx, fmaf(dy, dy, dz*dz));
        float ch  = fmaxf(fabsf(dx), fmaxf(fabsf(dy), fabsf(dz)));
        float dd  = (ch <= 4.8f) ? dsq : INF;
        ins3(dd, t, d0, i0, d1, i1, d2v, i2);
    }

    // butterfly all-reduce merge: every lane ends with global top-3
    #pragma unroll
    for (int s = 16; s; s >>= 1) {
        float e0 = __shfl_xor_sync(0xffffffffu, d0,  s);
        int   j0 = __shfl_xor_sync(0xffffffffu, i0,  s);
        float e1 = __shfl_xor_sync(0xffffffffu, d1,  s);
        int   j1 = __shfl_xor_sync(0xffffffffu, i1,  s);
        float e2 = __shfl_xor_sync(0xffffffffu, d2v, s);
        int   j2 = __shfl_xor_sync(0xffffffffu, i2,  s);
        ins3(e0, j0, d0, i0, d1, i1, d2v, i2);
        ins3(e1, j1, d0, i0, d1, i1, d2v, i2);
        ins3(e2, j2, d0, i0, d1, i1, d2v, i2);
    }

    const bool fin0 = d0  < INF;
    const bool fin1 = d1  < INF;
    const bool fin2 = d2v < INF;
    const bool empty = !fin0;
    float r0 = fin0 ? 1.0f/(d0  + 1e-8f) : 0.0f;
    float r1 = fin1 ? 1.0f/(d1  + 1e-8f) : 0.0f;
    float r2 = fin2 ? 1.0f/(d2v + 1e-8f) : 0.0f;
    float s  = fmaxf(r0 + r1 + r2, 1e-8f);
    float w0 = r0 / s, w1 = r1 / s, w2 = r2 / s;
    if (i0 < 0) i0 = 0;
    if (i1 < 0) i1 = i0;
    if (i2 < 0) i2 = i0;

    const float* F = g_feats + batch*NN*32;
    float* vb = g_vec + cid*VPITCH;

    // 32 feature channels (one per lane)
    float f = w0*F[i0*32 + lane] + w1*F[i1*32 + lane] + w2*F[i2*32 + lane];
    vb[lane] = empty ? 0.0f : f;

    // 9 local xyz offsets (lanes 0..8)
    if (lane < 9) {
        int k = lane / 3, j = lane - k*3;
        int ik = (k == 0) ? i0 : ((k == 1) ? i1 : i2);
        const float* pp = (const float*)&spt[ik];
        float cj = (j == 0) ? cx : ((j == 1) ? cy : cz);
        vb[32 + lane] = empty ? 0.0f : (cj - pp[j]);
    }
}

// ---------------------------------------------------------------------------
// K2: grouped 1x1 conv (41 -> 32 per voxel) + BN1 + ReLU
// grid (BM/32, G); block 256; one warp = one m row, 32 outputs (one/lane)
// ---------------------------------------------------------------------------
__global__ __launch_bounds__(256) void k_group(
        const float* __restrict__ wg, const float* __restrict__ g1,
        const float* __restrict__ b1, const float* __restrict__ mu1,
        const float* __restrict__ v1) {
    __shared__ float sw[32*43];     // pitch 43 -> conflict-free lane reads
    __shared__ float sv[8][44];
    const int g = blockIdx.y;
    const int tid = threadIdx.x;

    for (int t = tid; t < 32*41; t += 256) {
        int o = t / 41, i = t - o*41;
        sw[o*43 + i] = wg[g*(32*41) + t];
    }
    __syncthreads();

    const int warp = tid >> 5, lane = tid & 31;
    const int gc = g*32 + lane;
    const float scale = g1[gc] * rsqrtf(v1[gc] + 1e-5f);
    const float shift = b1[gc] - mu1[gc]*scale;

    for (int mm = 0; mm < 4; ++mm) {
        int m = blockIdx.x*32 + warp*4 + mm;
        const float* vr = g_vec + (m*GG + g)*VPITCH;
        sv[warp][lane] = vr[lane];
        if (lane < 9) sv[warp][32 + lane] = vr[32 + lane];
        __syncwarp();
        float acc = 0.0f;
        #pragma unroll
        for (int i = 0; i < 41; ++i)
            acc = fmaf(sv[warp][i], sw[lane*43 + i], acc);
        g_x[m*GC + gc] = fmaxf(fmaf(acc, scale, shift), 0.0f);
        __syncwarp();
    }
}

// ---------------------------------------------------------------------------
// K3: post MLP 1024x128 <- 1024x864 @ 864x128^T  + BN2 + ReLU
// tiles: 32m x 64c, k-chunks of 32; 256 threads; 8 outputs/thread (2m x 4c)
// ---------------------------------------------------------------------------
__global__ __launch_bounds__(256) void k_post(
        const float* __restrict__ wp, const float* __restrict__ g2,
        const float* __restrict__ b2, const float* __restrict__ mu2,
        const float* __restrict__ v2, float* __restrict__ out) {
    __shared__ float sA[32][33];
    __shared__ float sB[64][33];
    const int tid = threadIdx.x;
    const int cq = tid & 15;      // 16 groups x 4 c
    const int mq = tid >> 4;      // 16 groups x 2 m
    const int m0 = blockIdx.x * 32;
    const int c0 = blockIdx.y * 64;

    float acc[2][4] = {};

    for (int kb = 0; kb < GC; kb += 32) {
        {
            int r = tid >> 3, k4 = (tid & 7) * 4;
            float4 v = *(const float4*)(g_x + (m0 + r)*GC + kb + k4);
            sA[r][k4] = v.x; sA[r][k4+1] = v.y; sA[r][k4+2] = v.z; sA[r][k4+3] = v.w;
        }
        {
            int r = tid >> 3, k4 = (tid & 7) * 4;
            float4 v = *(const float4*)(wp + (c0 + r)*GC + kb + k4);
            sB[r][k4] = v.x; sB[r][k4+1] = v.y; sB[r][k4+2] = v.z; sB[r][k4+3] = v.w;
            float4 u = *(const float4*)(wp + (c0 + r + 32)*GC + kb + k4);
            sB[r+32][k4] = u.x; sB[r+32][k4+1] = u.y; sB[r+32][k4+2] = u.z; sB[r+32][k4+3] = u.w;
        }
        __syncthreads();
        #pragma unroll
        for (int k = 0; k < 32; ++k) {
            float a0 = sA[mq*2 + 0][k];
            float a1 = sA[mq*2 + 1][k];
            float w0 = sB[cq*4 + 0][k];
            float w1 = sB[cq*4 + 1][k];
            float w2 = sB[cq*4 + 2][k];
            float w3 = sB[cq*4 + 3][k];
            acc[0][0] = fmaf(a0, w0, acc[0][0]);
            acc[0][1] = fmaf(a0, w1, acc[0][1]);
            acc[0][2] = fmaf(a0, w2, acc[0][2]);
            acc[0][3] = fmaf(a0, w3, acc[0][3]);
            acc[1][0] = fmaf(a1, w0, acc[1][0]);
            acc[1][1] = fmaf(a1, w1, acc[1][1]);
            acc[1][2] = fmaf(a1, w2, acc[1][2]);
            acc[1][3] = fmaf(a1, w3, acc[1][3]);
        }
        __syncthreads();
    }

    #pragma unroll
    for (int j = 0; j < 4; ++j) {
        int c = c0 + cq*4 + j;
        float scale = g2[c] * rsqrtf(v2[c] + 1e-5f);
        float shift = b2[c] - mu2[c]*scale;
        #pragma unroll
        for (int r = 0; r < 2; ++r) {
            int m = m0 + mq*2 + r;
            out[m*CPOST + c] = fmaxf(fmaf(acc[r][j], scale, shift), 0.0f);
        }
    }
}

// ---------------------------------------------------------------------------
extern "C" void kernel_launch(void* const* d_in, const int* in_sizes, int n_in,
                              void* d_out, int out_size) {
    const float* sxyz  = (const float*)d_in[0];
    const float* sfeat = (const float*)d_in[1];
    const float* nxyz  = (const float*)d_in[2];
    const float* wg    = (const float*)d_in[3];
    const float* g1    = (const float*)d_in[4];
    const float* b1    = (const float*)d_in[5];
    const float* m1    = (const float*)d_in[6];
    const float* v1    = (const float*)d_in[7];
    const float* wp    = (const float*)d_in[8];
    const float* g2    = (const float*)d_in[9];
    const float* b2    = (const float*)d_in[10];
    const float* m2    = (const float*)d_in[11];
    const float* v2    = (const float*)d_in[12];
    float* out = (float*)d_out;

    k_reduce<<<(BB*NN*32 + 255)/256, 256>>>(sfeat);
    k_interp<<<NCENT/8, 256>>>(sxyz, nxyz);
    dim3 gg(BM/32, GG);
    k_group<<<gg, 256>>>(wg, g1, b1, m1, v1);
    dim3 gp(BM/32, CPOST/64);
    k_post<<<gp, 256>>>(wp, g2, b2, m2, v2, out);
}

// round 2
// speedup vs baseline: 1.1932x; 1.1932x over previous
#include <cuda_runtime.h>
#include <math_constants.h>

#define BB 2
#define NN 2048
#define MM 512
#define GG 27
#define CAGG 32
#define CPOST 128
#define GC (GG*CAGG)      // 864
#define BM (BB*MM)        // 1024
#define NCELL 512         // 8^3 grid
#define HCELL 1.25f
#define INVH 0.8f
#define KSPLIT 4

// Scratch (device globals; allocation is forbidden)
__device__ __align__(16) float4 g_pts4[BB][NN];          // binned points (xyz)
__device__ int   g_cstart[BB][NCELL+1];
__device__ int   g_perm[BB][NN];                          // binned pos -> orig idx
__device__ __align__(16) float g_feats[BB*NN*32];        // binned reduced features
__device__ __align__(16) float g_x[BM*GC];               // grouped-conv output
__device__ __align__(16) float g_part[KSPLIT][BM*CPOST]; // split-K partials

// ---------------------------------------------------------------------------
// K_bin: per-batch counting sort of support points into 8^3 cells
// ---------------------------------------------------------------------------
__global__ __launch_bounds__(256) void k_bin(const float* __restrict__ sxyz) {
    __shared__ int cnt[NCELL];
    __shared__ int start[NCELL+1];
    const int b = blockIdx.x;
    const int tid = threadIdx.x;
    for (int c = tid; c < NCELL; c += 256) cnt[c] = 0;
    __syncthreads();
    for (int p = tid; p < NN; p += 256) {
        const float* s = sxyz + (b*NN + p)*3;
        int cx = min(max((int)floorf(s[0]*INVH), 0), 7);
        int cy = min(max((int)floorf(s[1]*INVH), 0), 7);
        int cz = min(max((int)floorf(s[2]*INVH), 0), 7);
        atomicAdd(&cnt[(cx*8+cy)*8+cz], 1);
    }
    __syncthreads();
    if (tid < 32) {                      // warp-parallel prefix sum over 512
        int base = tid*16, s = 0;
        #pragma unroll
        for (int i = 0; i < 16; ++i) s += cnt[base+i];
        int inc = s;
        #pragma unroll
        for (int o = 1; o < 32; o <<= 1) {
            int v = __shfl_up_sync(0xffffffffu, inc, o);
            if (tid >= o) inc += v;
        }
        int run = inc - s;               // exclusive
        #pragma unroll
        for (int i = 0; i < 16; ++i) { start[base+i] = run; run += cnt[base+i]; }
        if (tid == 31) start[NCELL] = run;
    }
    __syncthreads();
    for (int c = tid; c < NCELL; c += 256) cnt[c] = start[c];
    __syncthreads();
    for (int p = tid; p < NN; p += 256) {
        const float* s = sxyz + (b*NN + p)*3;
        float x = s[0], y = s[1], z = s[2];
        int cx = min(max((int)floorf(x*INVH), 0), 7);
        int cy = min(max((int)floorf(y*INVH), 0), 7);
        int cz = min(max((int)floorf(z*INVH), 0), 7);
        int pos = atomicAdd(&cnt[(cx*8+cy)*8+cz], 1);
        g_pts4[b][pos] = make_float4(x, y, z, 0.0f);
        g_perm[b][pos] = p;
    }
    for (int c = tid; c <= NCELL; c += 256) g_cstart[b][c] = start[c];
}

// ---------------------------------------------------------------------------
// K_reduce: channel reduction 128->32 gathered into binned order
// ---------------------------------------------------------------------------
__global__ void k_reduce(const float* __restrict__ sf) {
    int t = blockIdx.x * 256 + threadIdx.x;
    if (t >= BB*NN*32) return;
    int row = t >> 5, c = t & 31;
    int b = row / NN, p = row - b*NN;
    int orig = g_perm[b][p];
    const float* q = sf + (b*NN + orig)*128 + c;
    g_feats[t] = q[0] + q[32] + q[64] + q[96];
}

// Branchless insert of (d,i) into sorted triple d0<=d1<=d2
__device__ __forceinline__ void ins3(float d, int i,
        float& d0, int& i0, float& d1, int& i1, float& d2, int& i2) {
    bool c2 = d < d2, c1 = d < d1, c0 = d < d0;
    d2 = c1 ? d1 : (c2 ? d : d2);  i2 = c1 ? i1 : (c2 ? i : i2);
    d1 = c0 ? d0 : (c1 ? d : d1);  i1 = c0 ? i0 : (c1 ? i : i1);
    d0 = c0 ? d  : d0;             i0 = c0 ? i  : i0;
}

// ---------------------------------------------------------------------------
// K1: grid-accelerated 3-NN + interp + fused grouped conv + BN1 + ReLU
// grid (BM/128, GG); block 128; one thread = one center (m, g)
// ---------------------------------------------------------------------------
__global__ __launch_bounds__(128) void k1(
        const float* __restrict__ nxyz, const float* __restrict__ wg,
        const float* __restrict__ g1, const float* __restrict__ b1,
        const float* __restrict__ mu1, const float* __restrict__ v1) {
    __shared__ float4 pts[NN];           // 32 KB binned points
    __shared__ int    cst[NCELL+1];
    __shared__ float  swT[41*CAGG];      // weights transposed: [i][o]
    __shared__ float  sscale[CAGG], sshift[CAGG];
    __shared__ float  snx[128*3];
    const int tid = threadIdx.x;
    const int g   = blockIdx.y;
    const int m0  = blockIdx.x * 128;
    const int b   = m0 / MM;

    {
        const float4* gp = g_pts4[b];
        for (int i = tid; i < NN; i += 128) pts[i] = gp[i];
        for (int i = tid; i < NCELL+1; i += 128) cst[i] = g_cstart[b][i];
        for (int i = tid; i < 41*CAGG; i += 128) {
            int ii = i >> 5, o = i & 31;                 // i = ii*32+o
            swT[i] = wg[g*CAGG*41 + o*41 + ii];
        }
        for (int i = tid; i < 128*3; i += 128) snx[i] = nxyz[m0*3 + i];
        if (tid < CAGG) {
            int gc = g*CAGG + tid;
            float sc = g1[gc] * rsqrtf(v1[gc] + 1e-5f);
            sscale[tid] = sc;
            sshift[tid] = b1[gc] - mu1[gc]*sc;
        }
    }
    __syncthreads();

    const int m = m0 + tid;
    const int ixg = g / 9;
    const int iyg = (g - ixg*9) / 3;
    const int izg = g - ixg*9 - iyg*3;
    const float cx = snx[tid*3+0] + __fadd_rn(__fmul_rn((float)ixg + 0.5f, 1.6f), -2.4f);
    const float cy = snx[tid*3+1] + __fadd_rn(__fmul_rn((float)iyg + 0.5f, 1.6f), -2.4f);
    const float cz = snx[tid*3+2] + __fadd_rn(__fmul_rn((float)izg + 0.5f, 1.6f), -2.4f);
    const int icx = (int)floorf(cx * INVH);
    const int icy = (int)floorf(cy * INVH);
    const int icz = (int)floorf(cz * INVH);

    const float INF = CUDART_INF_F;
    float d0 = INF, d1 = INF, d2v = INF;
    int   i0 = -1,  i1 = -1,  i2 = -1;

    for (int r = 0; r <= 10; ++r) {
        int xlo = max(icx - r, 0), xhi = min(icx + r, 7);
        int ylo = max(icy - r, 0), yhi = min(icy + r, 7);
        int zlo = max(icz - r, 0), zhi = min(icz + r, 7);
        for (int x = xlo; x <= xhi; ++x)
        for (int y = ylo; y <= yhi; ++y)
        for (int z = zlo; z <= zhi; ++z) {
            // shell only: skip interior cells (already scanned in prior rings)
            if (r > 0 && abs(x-icx) < r && abs(y-icy) < r && abs(z-icz) < r) continue;
            int cell = (x*8 + y)*8 + z;
            int s = cst[cell], e = cst[cell+1];
            for (int j = s; j < e; ++j) {
                float4 p = pts[j];
                float dx = cx - p.x, dy = cy - p.y, dz = cz - p.z;
                float dsq = fmaf(dx, dx, fmaf(dy, dy, dz*dz));
                float ch  = fmaxf(fabsf(dx), fmaxf(fabsf(dy), fabsf(dz)));
                float dd  = (ch <= 4.8f) ? dsq : INF;
                ins3(dd, j, d0, i0, d1, i1, d2v, i2);
            }
        }
        float bound = fmaxf((float)r * HCELL - 1e-3f, 0.0f);   // fp-safety margin
        if (d2v <= bound*bound) break;
    }

    const bool empty = !(d0 < INF);
    float r0 = (d0  < INF) ? 1.0f/(d0  + 1e-8f) : 0.0f;
    float r1 = (d1  < INF) ? 1.0f/(d1  + 1e-8f) : 0.0f;
    float r2 = (d2v < INF) ? 1.0f/(d2v + 1e-8f) : 0.0f;
    float ssum = fmaxf(r0 + r1 + r2, 1e-8f);
    float w0 = r0/ssum, w1 = r1/ssum, w2 = r2/ssum;
    if (i0 < 0) i0 = 0;
    if (i1 < 0) i1 = i0;
    if (i2 < 0) i2 = i0;

    float vec[41];
    {
        const float4* F0 = (const float4*)(g_feats + (b*NN + i0)*32);
        const float4* F1 = (const float4*)(g_feats + (b*NN + i1)*32);
        const float4* F2 = (const float4*)(g_feats + (b*NN + i2)*32);
        #pragma unroll
        for (int q = 0; q < 8; ++q) {
            float4 a = F0[q], u = F1[q], v = F2[q];
            vec[q*4+0] = w0*a.x + w1*u.x + w2*v.x;
            vec[q*4+1] = w0*a.y + w1*u.y + w2*v.y;
            vec[q*4+2] = w0*a.z + w1*u.z + w2*v.z;
            vec[q*4+3] = w0*a.w + w1*u.w + w2*v.w;
        }
        float4 p0 = pts[i0], p1 = pts[i1], p2 = pts[i2];
        vec[32] = cx - p0.x; vec[33] = cy - p0.y; vec[34] = cz - p0.z;
        vec[35] = cx - p1.x; vec[36] = cy - p1.y; vec[37] = cz - p1.z;
        vec[38] = cx - p2.x; vec[39] = cy - p2.y; vec[40] = cz - p2.z;
        if (empty) {
            #pragma unroll
            for (int i = 0; i < 41; ++i) vec[i] = 0.0f;
        }
    }

    // fused grouped conv (41 -> 32) + BN1 + ReLU
    float* xo = g_x + m*GC + g*CAGG;
    #pragma unroll
    for (int oc = 0; oc < 32; oc += 8) {
        float acc[8] = {0,0,0,0,0,0,0,0};
        #pragma unroll
        for (int i = 0; i < 41; ++i) {
            float vi = vec[i];
            float4 wa = *(const float4*)&swT[i*32 + oc];
            float4 wb = *(const float4*)&swT[i*32 + oc + 4];
            acc[0] = fmaf(vi, wa.x, acc[0]);
            acc[1] = fmaf(vi, wa.y, acc[1]);
            acc[2] = fmaf(vi, wa.z, acc[2]);
            acc[3] = fmaf(vi, wa.w, acc[3]);
            acc[4] = fmaf(vi, wb.x, acc[4]);
            acc[5] = fmaf(vi, wb.y, acc[5]);
            acc[6] = fmaf(vi, wb.z, acc[6]);
            acc[7] = fmaf(vi, wb.w, acc[7]);
        }
        #pragma unroll
        for (int o = 0; o < 8; ++o)
            xo[oc+o] = fmaxf(fmaf(acc[o], sscale[oc+o], sshift[oc+o]), 0.0f);
    }
}

// ---------------------------------------------------------------------------
// K_post: split-K GEMM 1024x128 <- 1024x864 @ (128x864)^T, partials only
// grid (32, 2, KSPLIT); block 256; tile 32m x 64c; k chunks of 32
// ---------------------------------------------------------------------------
__global__ __launch_bounds__(256) void k_post(const float* __restrict__ wp) {
    __shared__ float sA[32][33];
    __shared__ float sB[64][33];
    const int tid = threadIdx.x;
    const int cq = tid & 15;
    const int mq = tid >> 4;
    const int m0 = blockIdx.x * 32;
    const int c0 = blockIdx.y * 64;
    const int ks = blockIdx.z;
    const int kb_lo = ((27*ks)   / KSPLIT) * 32;
    const int kb_hi = ((27*(ks+1))/ KSPLIT) * 32;

    float acc[2][4] = {};

    for (int kb = kb_lo; kb < kb_hi; kb += 32) {
        {
            int r = tid >> 3, k4 = (tid & 7) * 4;
            float4 v = *(const float4*)(g_x + (m0 + r)*GC + kb + k4);
            sA[r][k4] = v.x; sA[r][k4+1] = v.y; sA[r][k4+2] = v.z; sA[r][k4+3] = v.w;
            float4 w0 = *(const float4*)(wp + (c0 + r)*GC + kb + k4);
            sB[r][k4] = w0.x; sB[r][k4+1] = w0.y; sB[r][k4+2] = w0.z; sB[r][k4+3] = w0.w;
            float4 w1 = *(const float4*)(wp + (c0 + r + 32)*GC + kb + k4);
            sB[r+32][k4] = w1.x; sB[r+32][k4+1] = w1.y; sB[r+32][k4+2] = w1.z; sB[r+32][k4+3] = w1.w;
        }
        __syncthreads();
        #pragma unroll
        for (int k = 0; k < 32; ++k) {
            float a0 = sA[mq*2 + 0][k];
            float a1 = sA[mq*2 + 1][k];
            float w0 = sB[cq*4 + 0][k];
            float w1 = sB[cq*4 + 1][k];
            float w2 = sB[cq*4 + 2][k];
            float w3 = sB[cq*4 + 3][k];
            acc[0][0] = fmaf(a0, w0, acc[0][0]);
            acc[0][1] = fmaf(a0, w1, acc[0][1]);
            acc[0][2] = fmaf(a0, w2, acc[0][2]);
            acc[0][3] = fmaf(a0, w3, acc[0][3]);
            acc[1][0] = fmaf(a1, w0, acc[1][0]);
            acc[1][1] = fmaf(a1, w1, acc[1][1]);
            acc[1][2] = fmaf(a1, w2, acc[1][2]);
            acc[1][3] = fmaf(a1, w3, acc[1][3]);
        }
        __syncthreads();
    }

    float* dst = g_part[ks];
    #pragma unroll
    for (int j = 0; j < 4; ++j) {
        int c = c0 + cq*4 + j;
        #pragma unroll
        for (int r = 0; r < 2; ++r) {
            int m = m0 + mq*2 + r;
            dst[m*CPOST + c] = acc[r][j];
        }
    }
}

// ---------------------------------------------------------------------------
// K_fin: sum split-K partials + BN2 + ReLU
// ---------------------------------------------------------------------------
__global__ void k_fin(const float* __restrict__ g2, const float* __restrict__ b2,
                      const float* __restrict__ mu2, const float* __restrict__ v2,
                      float* __restrict__ out) {
    int t = blockIdx.x * 256 + threadIdx.x;
    if (t >= BM*CPOST) return;
    int c = t & 127;
    float s = ((g_part[0][t] + g_part[1][t]) + g_part[2][t]) + g_part[3][t];
    float scale = g2[c] * rsqrtf(v2[c] + 1e-5f);
    float shift = b2[c] - mu2[c]*scale;
    out[t] = fmaxf(fmaf(s, scale, shift), 0.0f);
}

// ---------------------------------------------------------------------------
extern "C" void kernel_launch(void* const* d_in, const int* in_sizes, int n_in,
                              void* d_out, int out_size) {
    const float* sxyz  = (const float*)d_in[0];
    const float* sfeat = (const float*)d_in[1];
    const float* nxyz  = (const float*)d_in[2];
    const float* wg    = (const float*)d_in[3];
    const float* g1    = (const float*)d_in[4];
    const float* b1    = (const float*)d_in[5];
    const float* m1    = (const float*)d_in[6];
    const float* v1    = (const float*)d_in[7];
    const float* wp    = (const float*)d_in[8];
    const float* g2    = (const float*)d_in[9];
    const float* b2    = (const float*)d_in[10];
    const float* m2    = (const float*)d_in[11];
    const float* v2    = (const float*)d_in[12];
    float* out = (float*)d_out;

    k_bin<<<BB, 256>>>(sxyz);
    k_reduce<<<(BB*NN*32 + 255)/256, 256>>>(sfeat);
    k1<<<dim3(BM/128, GG), 128>>>(nxyz, wg, g1, b1, m1, v1);
    k_post<<<dim3(BM/32, CPOST/64, KSPLIT), 256>>>(wp);
    k_fin<<<(BM*CPOST + 255)/256, 256>>>(g2, b2, m2, v2, out);
}

// round 4
// speedup vs baseline: 1.4084x; 1.1804x over previous
#include <cuda_runtime.h>
#include <math_constants.h>

#define BB 2
#define NN 2048
#define MM 512
#define GG 27
#define CAGG 32
#define CPOST 128
#define GC (GG*CAGG)      // 864
#define BM (BB*MM)        // 1024
#define NCENT (BM*GG)     // 27648
#define NCELL 512         // 8^3 grid
#define HCELL 1.25f
#define INVH 0.8f
#define KSPLIT 9
#define VPITCH 48

// Scratch (device globals; allocation is forbidden)
__device__ __align__(16) float4 g_pts4[BB][NN];          // binned points
__device__ int   g_cstart[BB][NCELL+1];
__device__ int   g_perm[BB][NN];
__device__ __align__(16) float g_feats[BB*NN*32];        // binned reduced feats
__device__ __align__(16) float g_vec[NCENT*VPITCH];      // interp vectors
__device__ __align__(16) float g_x[BM*GC];               // grouped-conv out
__device__ __align__(16) float g_part[KSPLIT][BM*CPOST]; // split-K partials

// ---------------------------------------------------------------------------
// K_bin: per-batch counting sort of support points into 8^3 cells
// ---------------------------------------------------------------------------
__global__ __launch_bounds__(256) void k_bin(const float* __restrict__ sxyz) {
    __shared__ int cnt[NCELL];
    __shared__ int start[NCELL+1];
    const int b = blockIdx.x;
    const int tid = threadIdx.x;
    for (int c = tid; c < NCELL; c += 256) cnt[c] = 0;
    __syncthreads();
    for (int p = tid; p < NN; p += 256) {
        const float* s = sxyz + (b*NN + p)*3;
        int cx = min(max((int)floorf(s[0]*INVH), 0), 7);
        int cy = min(max((int)floorf(s[1]*INVH), 0), 7);
        int cz = min(max((int)floorf(s[2]*INVH), 0), 7);
        atomicAdd(&cnt[(cx*8+cy)*8+cz], 1);
    }
    __syncthreads();
    if (tid < 32) {
        int base = tid*16, s = 0;
        #pragma unroll
        for (int i = 0; i < 16; ++i) s += cnt[base+i];
        int inc = s;
        #pragma unroll
        for (int o = 1; o < 32; o <<= 1) {
            int v = __shfl_up_sync(0xffffffffu, inc, o);
            if (tid >= o) inc += v;
        }
        int run = inc - s;
        #pragma unroll
        for (int i = 0; i < 16; ++i) { start[base+i] = run; run += cnt[base+i]; }
        if (tid == 31) start[NCELL] = run;
    }
    __syncthreads();
    for (int c = tid; c < NCELL; c += 256) cnt[c] = start[c];
    __syncthreads();
    for (int p = tid; p < NN; p += 256) {
        const float* s = sxyz + (b*NN + p)*3;
        float x = s[0], y = s[1], z = s[2];
        int cx = min(max((int)floorf(x*INVH), 0), 7);
        int cy = min(max((int)floorf(y*INVH), 0), 7);
        int cz = min(max((int)floorf(z*INVH), 0), 7);
        int pos = atomicAdd(&cnt[(cx*8+cy)*8+cz], 1);
        g_pts4[b][pos] = make_float4(x, y, z, 0.0f);
        g_perm[b][pos] = p;
    }
    for (int c = tid; c <= NCELL; c += 256) g_cstart[b][c] = start[c];
}

// ---------------------------------------------------------------------------
// K_reduce: channel reduction 128->32 gathered into binned order
// ---------------------------------------------------------------------------
__global__ void k_reduce(const float* __restrict__ sf) {
    int t = blockIdx.x * 256 + threadIdx.x;
    if (t >= BB*NN*32) return;
    int row = t >> 5, c = t & 31;
    int b = row / NN, p = row - b*NN;
    int orig = g_perm[b][p];
    const float* q = sf + (b*NN + orig)*128 + c;
    g_feats[t] = q[0] + q[32] + q[64] + q[96];
}

// Branchless insert of (d,i) into sorted triple d0<=d1<=d2
__device__ __forceinline__ void ins3(float d, int i,
        float& d0, int& i0, float& d1, int& i1, float& d2, int& i2) {
    bool c2 = d < d2, c1 = d < d1, c0 = d < d0;
    d2 = c1 ? d1 : (c2 ? d : d2);  i2 = c1 ? i1 : (c2 ? i : i2);
    d1 = c0 ? d0 : (c1 ? d : d1);  i1 = c0 ? i0 : (c1 ? i : i1);
    d0 = c0 ? d  : d0;             i0 = c0 ? i  : i0;
}

// ---------------------------------------------------------------------------
// K_nn: grid 3-NN per center with 8-lane groups. Writes g_vec[cid][41].
// block 256 = 32 groups; grid NCENT/32
// ---------------------------------------------------------------------------
__global__ __launch_bounds__(256) void k_nn(const float* __restrict__ nxyz) {
    __shared__ int cst[NCELL+1];
    const int tid = threadIdx.x;
    const int grp = tid >> 3;
    const int l   = tid & 7;
    const unsigned gmask = 0xffu << (tid & 24);
    const int cid = blockIdx.x*32 + grp;
    const int b   = (blockIdx.x*32) / (MM*GG);   // block never straddles batches

    for (int i = tid; i < NCELL+1; i += 256) cst[i] = g_cstart[b][i];
    __syncthreads();

    const int m = cid / GG, g = cid - m*GG;
    const int ixg = g / 9;
    const int iyg = (g - ixg*9) / 3;
    const int izg = g - ixg*9 - iyg*3;
    const float cx = nxyz[m*3+0] + __fadd_rn(__fmul_rn((float)ixg + 0.5f, 1.6f), -2.4f);
    const float cy = nxyz[m*3+1] + __fadd_rn(__fmul_rn((float)iyg + 0.5f, 1.6f), -2.4f);
    const float cz = nxyz[m*3+2] + __fadd_rn(__fmul_rn((float)izg + 0.5f, 1.6f), -2.4f);
    const int icx = (int)floorf(cx * INVH);
    const int icy = (int)floorf(cy * INVH);
    const int icz = (int)floorf(cz * INVH);

    const float INF = CUDART_INF_F;
    float d0 = INF, d1 = INF, d2v = INF;   // per-lane (disjoint point sets)
    int   i0 = -1,  i1 = -1,  i2 = -1;
    float td0, td1, td2; int ti0, ti1, ti2;

    const float4* __restrict__ pts = g_pts4[b];

    for (int r = 1; r <= 4; ++r) {
        if (r == 1) {
            // full 3x3x3 box, lanes stride cells
            for (int c = l; c < 27; c += 8) {
                int x = icx + c/9 - 1;
                int y = icy + (c/3)%3 - 1;
                int z = icz + c%3 - 1;
                if (x < 0 || x > 7 || y < 0 || y > 7 || z < 0 || z > 7) continue;
                int cell = (x*8 + y)*8 + z;
                int s = cst[cell], e = cst[cell+1];
                for (int j = s; j < e; ++j) {
                    float4 p = __ldg(&pts[j]);
                    float dx = cx - p.x, dy = cy - p.y, dz = cz - p.z;
                    float dsq = fmaf(dx, dx, fmaf(dy, dy, dz*dz));
                    float ch  = fmaxf(fabsf(dx), fmaxf(fabsf(dy), fabsf(dz)));
                    float dd  = (ch <= 4.8f) ? dsq : INF;
                    ins3(dd, j, d0, i0, d1, i1, d2v, i2);
                }
            }
        } else {
            // shell of box radius r
            int side = 2*r + 1, s2 = side*side, tot = side*s2;
            for (int t = l; t < tot; t += 8) {
                int q  = t / s2;
                int rm = t - q*s2;
                int dxc = q - r, dyc = rm/side - r, dzc = rm - (rm/side)*side - r;
                if (abs(dxc) < r && abs(dyc) < r && abs(dzc) < r) continue;
                int x = icx + dxc, y = icy + dyc, z = icz + dzc;
                if (x < 0 || x > 7 || y < 0 || y > 7 || z < 0 || z > 7) continue;
                int cell = (x*8 + y)*8 + z;
                int s = cst[cell], e = cst[cell+1];
                for (int j = s; j < e; ++j) {
                    float4 p = __ldg(&pts[j]);
                    float dx = cx - p.x, dy = cy - p.y, dz = cz - p.z;
                    float dsq = fmaf(dx, dx, fmaf(dy, dy, dz*dz));
                    float ch  = fmaxf(fabsf(dx), fmaxf(fabsf(dy), fabsf(dz)));
                    float dd  = (ch <= 4.8f) ? dsq : INF;
                    ins3(dd, j, d0, i0, d1, i1, d2v, i2);
                }
            }
        }
        // merge into temps (per-lane state stays pure/disjoint)
        td0 = d0; td1 = d1; td2 = d2v; ti0 = i0; ti1 = i1; ti2 = i2;
        #pragma unroll
        for (int s = 1; s < 8; s <<= 1) {
            float e0 = __shfl_xor_sync(gmask, td0, s);
            int   j0 = __shfl_xor_sync(gmask, ti0, s);
            float e1 = __shfl_xor_sync(gmask, td1, s);
            int   j1 = __shfl_xor_sync(gmask, ti1, s);
            float e2 = __shfl_xor_sync(gmask, td2, s);
            int   j2 = __shfl_xor_sync(gmask, ti2, s);
            ins3(e0, j0, td0, ti0, td1, ti1, td2, ti2);
            ins3(e1, j1, td0, ti0, td1, ti1, td2, ti2);
            ins3(e2, j2, td0, ti0, td1, ti1, td2, ti2);
        }
        float bound = (float)r * HCELL - 1e-3f;
        if (td2 <= bound*bound) break;
    }

    const bool empty = !(td0 < INF);
    float r0 = (td0 < INF) ? 1.0f/(td0 + 1e-8f) : 0.0f;
    float r1 = (td1 < INF) ? 1.0f/(td1 + 1e-8f) : 0.0f;
    float r2 = (td2 < INF) ? 1.0f/(td2 + 1e-8f) : 0.0f;
    float ssum = fmaxf(r0 + r1 + r2, 1e-8f);
    float w0 = r0/ssum, w1 = r1/ssum, w2 = r2/ssum;
    if (ti0 < 0) ti0 = 0;
    if (ti1 < 0) ti1 = ti0;
    if (ti2 < 0) ti2 = ti0;

    // interp: lane handles 4 feature channels (float4)
    const float4* F0 = (const float4*)(g_feats + (b*NN + ti0)*32);
    const float4* F1 = (const float4*)(g_feats + (b*NN + ti1)*32);
    const float4* F2 = (const float4*)(g_feats + (b*NN + ti2)*32);
    float4 a = __ldg(&F0[l]), u = __ldg(&F1[l]), v = __ldg(&F2[l]);
    float4 f;
    f.x = w0*a.x + w1*u.x + w2*v.x;
    f.y = w0*a.y + w1*u.y + w2*v.y;
    f.z = w0*a.z + w1*u.z + w2*v.z;
    f.w = w0*a.w + w1*u.w + w2*v.w;
    if (empty) f = make_float4(0.f, 0.f, 0.f, 0.f);
    float* vb = g_vec + cid*VPITCH;
    ((float4*)vb)[l] = f;

    if (l < 3) {
        int isel = (l == 0) ? ti0 : ((l == 1) ? ti1 : ti2);
        float4 p = __ldg(&pts[isel]);
        vb[32 + l*3 + 0] = empty ? 0.0f : (cx - p.x);
        vb[32 + l*3 + 1] = empty ? 0.0f : (cy - p.y);
        vb[32 + l*3 + 2] = empty ? 0.0f : (cz - p.z);
    }
}

// ---------------------------------------------------------------------------
// K_group: grouped 1x1 conv (41 -> 32 per voxel) + BN1 + ReLU
// grid (BM/32, G); block 256; one warp = one m row, 32 outputs (one/lane)
// ---------------------------------------------------------------------------
__global__ __launch_bounds__(256) void k_group(
        const float* __restrict__ wg, const float* __restrict__ g1,
        const float* __restrict__ b1, const float* __restrict__ mu1,
        const float* __restrict__ v1) {
    __shared__ float sw[32*43];
    __shared__ float sv[8][44];
    const int g = blockIdx.y;
    const int tid = threadIdx.x;

    for (int t = tid; t < 32*41; t += 256) {
        int o = t / 41, i = t - o*41;
        sw[o*43 + i] = wg[g*(32*41) + t];
    }
    __syncthreads();

    const int warp = tid >> 5, lane = tid & 31;
    const int gc = g*32 + lane;
    const float scale = g1[gc] * rsqrtf(v1[gc] + 1e-5f);
    const float shift = b1[gc] - mu1[gc]*scale;

    for (int mm = 0; mm < 4; ++mm) {
        int m = blockIdx.x*32 + warp*4 + mm;
        const float* vr = g_vec + (m*GG + g)*VPITCH;
        sv[warp][lane] = vr[lane];
        if (lane < 9) sv[warp][32 + lane] = vr[32 + lane];
        __syncwarp();
        float acc = 0.0f;
        #pragma unroll
        for (int i = 0; i < 41; ++i)
            acc = fmaf(sv[warp][i], sw[lane*43 + i], acc);
        g_x[m*GC + gc] = fmaxf(fmaf(acc, scale, shift), 0.0f);
        __syncwarp();
    }
}

// ---------------------------------------------------------------------------
// K_post: split-K GEMM partials. CTA tile 64m x 128n, k=96 per split.
// block 128 (tx 0..15 over n, ty 0..7 over m), thread tile 8x8.
// smem k-major; pitches 68 / 132 (multiple of 4 -> aligned float4 reads).
// ---------------------------------------------------------------------------
__global__ __launch_bounds__(128) void k_post(const float* __restrict__ wp) {
    __shared__ float sA[32][68];    // [k][m], pitch 68 keeps float4 alignment
    __shared__ float sB[32][132];   // [k][n], pitch 132
    const int tid = threadIdx.x;
    const int tx = tid & 15;
    const int ty = tid >> 4;
    const int m0 = blockIdx.x * 64;
    const int kb0 = blockIdx.y * 96;

    float acc[8][8];
    #pragma unroll
    for (int i = 0; i < 8; ++i)
        #pragma unroll
        for (int j = 0; j < 8; ++j) acc[i][j] = 0.0f;

    for (int kc = 0; kc < 96; kc += 32) {
        const int kb = kb0 + kc;
        #pragma unroll
        for (int i = 0; i < 4; ++i) {               // A: 64m x 32k
            int f = tid + i*128;
            int mm = f >> 3, kq = (f & 7) << 2;
            float4 vv = *(const float4*)(g_x + (m0+mm)*GC + kb + kq);
            sA[kq+0][mm] = vv.x; sA[kq+1][mm] = vv.y;
            sA[kq+2][mm] = vv.z; sA[kq+3][mm] = vv.w;
        }
        #pragma unroll
        for (int i = 0; i < 8; ++i) {               // B: 128n x 32k
            int f = tid + i*128;
            int nr = f >> 3, kq = (f & 7) << 2;
            float4 vv = *(const float4*)(wp + nr*GC + kb + kq);
            sB[kq+0][nr] = vv.x; sB[kq+1][nr] = vv.y;
            sB[kq+2][nr] = vv.z; sB[kq+3][nr] = vv.w;
        }
        __syncthreads();
        #pragma unroll
        for (int k = 0; k < 32; ++k) {
            float av[8], bv[8];
            *(float4*)&av[0] = *(const float4*)&sA[k][ty*8];
            *(float4*)&av[4] = *(const float4*)&sA[k][ty*8 + 4];
            *(float4*)&bv[0] = *(const float4*)&sB[k][tx*4];
            *(float4*)&bv[4] = *(const float4*)&sB[k][64 + tx*4];
            #pragma unroll
            for (int i = 0; i < 8; ++i)
                #pragma unroll
                for (int j = 0; j < 8; ++j)
                    acc[i][j] = fmaf(av[i], bv[j], acc[i][j]);
        }
        __syncthreads();
    }

    float* dst = g_part[blockIdx.y];
    #pragma unroll
    for (int i = 0; i < 8; ++i) {
        int mrow = m0 + ty*8 + i;
        *(float4*)(dst + mrow*CPOST + tx*4)      = *(float4*)&acc[i][0];
        *(float4*)(dst + mrow*CPOST + 64 + tx*4) = *(float4*)&acc[i][4];
    }
}

// ---------------------------------------------------------------------------
// K_fin: sum split-K partials + BN2 + ReLU
// ---------------------------------------------------------------------------
__global__ void k_fin(const float* __restrict__ g2, const float* __restrict__ b2,
                      const float* __restrict__ mu2, const float* __restrict__ v2,
                      float* __restrict__ out) {
    int t = blockIdx.x * 256 + threadIdx.x;
    if (t >= BM*CPOST) return;
    int c = t & 127;
    float s = 0.0f;
    #pragma unroll
    for (int k = 0; k < KSPLIT; ++k) s += g_part[k][t];
    float scale = g2[c] * rsqrtf(v2[c] + 1e-5f);
    float shift = b2[c] - mu2[c]*scale;
    out[t] = fmaxf(fmaf(s, scale, shift), 0.0f);
}

// ---------------------------------------------------------------------------
extern "C" void kernel_launch(void* const* d_in, const int* in_sizes, int n_in,
                              void* d_out, int out_size) {
    const float* sxyz  = (const float*)d_in[0];
    const float* sfeat = (const float*)d_in[1];
    const float* nxyz  = (const float*)d_in[2];
    const float* wg    = (const float*)d_in[3];
    const float* g1    = (const float*)d_in[4];
    const float* b1    = (const float*)d_in[5];
    const float* m1    = (const float*)d_in[6];
    const float* v1    = (const float*)d_in[7];
    const float* wp    = (const float*)d_in[8];
    const float* g2    = (const float*)d_in[9];
    const float* b2    = (const float*)d_in[10];
    const float* m2    = (const float*)d_in[11];
    const float* v2    = (const float*)d_in[12];
    float* out = (float*)d_out;

    k_bin<<<BB, 256>>>(sxyz);
    k_reduce<<<(BB*NN*32 + 255)/256, 256>>>(sfeat);
    k_nn<<<NCENT/32, 256>>>(nxyz);
    k_group<<<dim3(BM/32, GG), 256>>>(wg, g1, b1, m1, v1);
    k_post<<<dim3(BM/64, KSPLIT), 128>>>(wp);
    k_fin<<<(BM*CPOST + 255)/256, 256>>>(g2, b2, m2, v2, out);
}

// round 5
// speedup vs baseline: 1.5547x; 1.1039x over previous
#include <cuda_runtime.h>
#include <math_constants.h>

#define BB 2
#define NN 2048
#define MM 512
#define GG 27
#define CAGG 32
#define CPOST 128
#define GC (GG*CAGG)      // 864
#define BM (BB*MM)        // 1024
#define NCENT (BM*GG)     // 27648
#define NCELL 512         // 8^3 grid
#define HCELL 1.25f
#define INVH 0.8f
#define KSPLIT 9
#define VPITCH 48

// Scratch (device globals; allocation is forbidden)
__device__ __align__(16) float4 g_pts4[BB][NN];          // binned points
__device__ int   g_cstart[BB][NCELL+1];
__device__ int   g_perm[BB][NN];
__device__ __align__(16) float g_feats[BB*NN*32];        // binned reduced feats
__device__ __align__(16) float g_vec[NCENT*VPITCH];      // interp vectors
__device__ __align__(16) float g_x[BM*GC];               // grouped-conv out
__device__ __align__(16) float g_part[KSPLIT][BM*CPOST]; // split-K partials

// ---------------------------------------------------------------------------
// K_bin: per-batch counting sort of support points into 8^3 cells
// ---------------------------------------------------------------------------
__global__ __launch_bounds__(256) void k_bin(const float* __restrict__ sxyz) {
    __shared__ int cnt[NCELL];
    __shared__ int start[NCELL+1];
    const int b = blockIdx.x;
    const int tid = threadIdx.x;
    for (int c = tid; c < NCELL; c += 256) cnt[c] = 0;
    __syncthreads();
    for (int p = tid; p < NN; p += 256) {
        const float* s = sxyz + (b*NN + p)*3;
        int cx = min(max((int)floorf(s[0]*INVH), 0), 7);
        int cy = min(max((int)floorf(s[1]*INVH), 0), 7);
        int cz = min(max((int)floorf(s[2]*INVH), 0), 7);
        atomicAdd(&cnt[(cx*8+cy)*8+cz], 1);
    }
    __syncthreads();
    if (tid < 32) {
        int base = tid*16, s = 0;
        #pragma unroll
        for (int i = 0; i < 16; ++i) s += cnt[base+i];
        int inc = s;
        #pragma unroll
        for (int o = 1; o < 32; o <<= 1) {
            int v = __shfl_up_sync(0xffffffffu, inc, o);
            if (tid >= o) inc += v;
        }
        int run = inc - s;
        #pragma unroll
        for (int i = 0; i < 16; ++i) { start[base+i] = run; run += cnt[base+i]; }
        if (tid == 31) start[NCELL] = run;
    }
    __syncthreads();
    for (int c = tid; c < NCELL; c += 256) cnt[c] = start[c];
    __syncthreads();
    for (int p = tid; p < NN; p += 256) {
        const float* s = sxyz + (b*NN + p)*3;
        float x = s[0], y = s[1], z = s[2];
        int cx = min(max((int)floorf(x*INVH), 0), 7);
        int cy = min(max((int)floorf(y*INVH), 0), 7);
        int cz = min(max((int)floorf(z*INVH), 0), 7);
        int pos = atomicAdd(&cnt[(cx*8+cy)*8+cz], 1);
        g_pts4[b][pos] = make_float4(x, y, z, 0.0f);
        g_perm[b][pos] = p;
    }
    for (int c = tid; c <= NCELL; c += 256) g_cstart[b][c] = start[c];
}

// ---------------------------------------------------------------------------
// K_reduce: channel reduction 128->32 gathered into binned order
// ---------------------------------------------------------------------------
__global__ void k_reduce(const float* __restrict__ sf) {
    int t = blockIdx.x * 256 + threadIdx.x;
    if (t >= BB*NN*32) return;
    int row = t >> 5, c = t & 31;
    int b = row / NN, p = row - b*NN;
    int orig = g_perm[b][p];
    const float* q = sf + (b*NN + orig)*128 + c;
    g_feats[t] = q[0] + q[32] + q[64] + q[96];
}

// Branchless insert of (d,i) into sorted triple d0<=d1<=d2
__device__ __forceinline__ void ins3(float d, int i,
        float& d0, int& i0, float& d1, int& i1, float& d2, int& i2) {
    bool c2 = d < d2, c1 = d < d1, c0 = d < d0;
    d2 = c1 ? d1 : (c2 ? d : d2);  i2 = c1 ? i1 : (c2 ? i : i2);
    d1 = c0 ? d0 : (c1 ? d : d1);  i1 = c0 ? i0 : (c1 ? i : i1);
    d0 = c0 ? d  : d0;             i0 = c0 ? i  : i0;
}

// ---------------------------------------------------------------------------
// K_nn: grid 3-NN per center with 16-lane groups. Writes g_vec[cid][41].
// block 256 = 16 groups; grid NCENT/16
// ---------------------------------------------------------------------------
__global__ __launch_bounds__(256) void k_nn(const float* __restrict__ nxyz) {
    __shared__ int cst[NCELL+1];
    const int tid = threadIdx.x;
    const int grp = tid >> 4;
    const int l   = tid & 15;
    const unsigned gmask = 0xffffu << (tid & 16);
    const int cid = blockIdx.x*16 + grp;
    const int b   = (blockIdx.x*16) / (MM*GG);   // 13824/16: never straddles

    for (int i = tid; i < NCELL+1; i += 256) cst[i] = g_cstart[b][i];
    __syncthreads();

    const int m = cid / GG, g = cid - m*GG;
    const int ixg = g / 9;
    const int iyg = (g - ixg*9) / 3;
    const int izg = g - ixg*9 - iyg*3;
    const float cx = nxyz[m*3+0] + __fadd_rn(__fmul_rn((float)ixg + 0.5f, 1.6f), -2.4f);
    const float cy = nxyz[m*3+1] + __fadd_rn(__fmul_rn((float)iyg + 0.5f, 1.6f), -2.4f);
    const float cz = nxyz[m*3+2] + __fadd_rn(__fmul_rn((float)izg + 0.5f, 1.6f), -2.4f);
    const int icx = (int)floorf(cx * INVH);
    const int icy = (int)floorf(cy * INVH);
    const int icz = (int)floorf(cz * INVH);

    const float INF = CUDART_INF_F;
    float d0 = INF, d1 = INF, d2v = INF;   // per-lane (disjoint point sets)
    int   i0 = -1,  i1 = -1,  i2 = -1;
    float td0, td1, td2; int ti0, ti1, ti2;

    const float4* __restrict__ pts = g_pts4[b];

    for (int r = 1; r <= 4; ++r) {
        if (r == 1) {
            for (int c = l; c < 27; c += 16) {
                int x = icx + c/9 - 1;
                int y = icy + (c/3)%3 - 1;
                int z = icz + c%3 - 1;
                if (x < 0 || x > 7 || y < 0 || y > 7 || z < 0 || z > 7) continue;
                int cell = (x*8 + y)*8 + z;
                int s = cst[cell], e = cst[cell+1];
                for (int j = s; j < e; ++j) {
                    float4 p = __ldg(&pts[j]);
                    float dx = cx - p.x, dy = cy - p.y, dz = cz - p.z;
                    float dsq = fmaf(dx, dx, fmaf(dy, dy, dz*dz));
                    float ch  = fmaxf(fabsf(dx), fmaxf(fabsf(dy), fabsf(dz)));
                    float dd  = (ch <= 4.8f) ? dsq : INF;
                    ins3(dd, j, d0, i0, d1, i1, d2v, i2);
                }
            }
        } else {
            int side = 2*r + 1, s2 = side*side, tot = side*s2;
            for (int t = l; t < tot; t += 16) {
                int q  = t / s2;
                int rm = t - q*s2;
                int dxc = q - r, dyc = rm/side - r, dzc = rm - (rm/side)*side - r;
                if (abs(dxc) < r && abs(dyc) < r && abs(dzc) < r) continue;
                int x = icx + dxc, y = icy + dyc, z = icz + dzc;
                if (x < 0 || x > 7 || y < 0 || y > 7 || z < 0 || z > 7) continue;
                int cell = (x*8 + y)*8 + z;
                int s = cst[cell], e = cst[cell+1];
                for (int j = s; j < e; ++j) {
                    float4 p = __ldg(&pts[j]);
                    float dx = cx - p.x, dy = cy - p.y, dz = cz - p.z;
                    float dsq = fmaf(dx, dx, fmaf(dy, dy, dz*dz));
                    float ch  = fmaxf(fabsf(dx), fmaxf(fabsf(dy), fabsf(dz)));
                    float dd  = (ch <= 4.8f) ? dsq : INF;
                    ins3(dd, j, d0, i0, d1, i1, d2v, i2);
                }
            }
        }
        // merge into temps (per-lane state stays pure/disjoint)
        td0 = d0; td1 = d1; td2 = d2v; ti0 = i0; ti1 = i1; ti2 = i2;
        #pragma unroll
        for (int s = 1; s < 16; s <<= 1) {
            float e0 = __shfl_xor_sync(gmask, td0, s);
            int   j0 = __shfl_xor_sync(gmask, ti0, s);
            float e1 = __shfl_xor_sync(gmask, td1, s);
            int   j1 = __shfl_xor_sync(gmask, ti1, s);
            float e2 = __shfl_xor_sync(gmask, td2, s);
            int   j2 = __shfl_xor_sync(gmask, ti2, s);
            ins3(e0, j0, td0, ti0, td1, ti1, td2, ti2);
            ins3(e1, j1, td0, ti0, td1, ti1, td2, ti2);
            ins3(e2, j2, td0, ti0, td1, ti1, td2, ti2);
        }
        float bound = (float)r * HCELL - 1e-3f;
        if (td2 <= bound*bound) break;
    }

    const bool empty = !(td0 < INF);
    float r0 = (td0 < INF) ? 1.0f/(td0 + 1e-8f) : 0.0f;
    float r1 = (td1 < INF) ? 1.0f/(td1 + 1e-8f) : 0.0f;
    float r2 = (td2 < INF) ? 1.0f/(td2 + 1e-8f) : 0.0f;
    float ssum = fmaxf(r0 + r1 + r2, 1e-8f);
    float w0 = r0/ssum, w1 = r1/ssum, w2 = r2/ssum;
    if (ti0 < 0) ti0 = 0;
    if (ti1 < 0) ti1 = ti0;
    if (ti2 < 0) ti2 = ti0;

    // interp: lane handles 2 feature channels (float2)
    const float2* F0 = (const float2*)(g_feats + (b*NN + ti0)*32);
    const float2* F1 = (const float2*)(g_feats + (b*NN + ti1)*32);
    const float2* F2 = (const float2*)(g_feats + (b*NN + ti2)*32);
    float2 a = __ldg(&F0[l]), u = __ldg(&F1[l]), v = __ldg(&F2[l]);
    float2 f;
    f.x = w0*a.x + w1*u.x + w2*v.x;
    f.y = w0*a.y + w1*u.y + w2*v.y;
    if (empty) f = make_float2(0.f, 0.f);
    float* vb = g_vec + cid*VPITCH;
    ((float2*)vb)[l] = f;

    if (l < 3) {
        int isel = (l == 0) ? ti0 : ((l == 1) ? ti1 : ti2);
        float4 p = __ldg(&pts[isel]);
        vb[32 + l*3 + 0] = empty ? 0.0f : (cx - p.x);
        vb[32 + l*3 + 1] = empty ? 0.0f : (cy - p.y);
        vb[32 + l*3 + 2] = empty ? 0.0f : (cz - p.z);
    }
}

// ---------------------------------------------------------------------------
// K_group: batched GEMM per voxel group. Block = (128 m-rows, one g).
// Thread owns one m-row: 41 inputs in registers, 32 outputs in registers,
// weights [i][o] in smem (broadcast LDS.128).  + BN1 + ReLU
// ---------------------------------------------------------------------------
__global__ __launch_bounds__(128) void k_group(
        const float* __restrict__ wg, const float* __restrict__ g1,
        const float* __restrict__ b1, const float* __restrict__ mu1,
        const float* __restrict__ v1) {
    __shared__ float sw[41*32];      // transposed: [i][o]
    __shared__ float ssc[CAGG], ssh[CAGG];
    const int g  = blockIdx.y;
    const int m  = blockIdx.x*128 + threadIdx.x;
    const int tid = threadIdx.x;

    for (int t = tid; t < 41*32; t += 128) {
        int o = t / 41, i = t - o*41;
        sw[i*32 + o] = wg[g*(32*41) + t];
    }
    if (tid < CAGG) {
        int gc = g*CAGG + tid;
        float sc = g1[gc] * rsqrtf(v1[gc] + 1e-5f);
        ssc[tid] = sc;
        ssh[tid] = b1[gc] - mu1[gc]*sc;
    }
    __syncthreads();

    // own row of g_vec into registers
    float vec[41];
    const float* vr = g_vec + (m*GG + g)*VPITCH;
    #pragma unroll
    for (int q = 0; q < 10; ++q) {
        float4 vv = *(const float4*)(vr + q*4);
        vec[q*4+0] = vv.x; vec[q*4+1] = vv.y; vec[q*4+2] = vv.z; vec[q*4+3] = vv.w;
    }
    vec[40] = vr[40];

    float4 acc[8];
    #pragma unroll
    for (int o4 = 0; o4 < 8; ++o4) acc[o4] = make_float4(0.f, 0.f, 0.f, 0.f);

    #pragma unroll
    for (int i = 0; i < 41; ++i) {
        float vi = vec[i];
        #pragma unroll
        for (int o4 = 0; o4 < 8; ++o4) {
            float4 w = *(const float4*)&sw[i*32 + o4*4];
            acc[o4].x = fmaf(vi, w.x, acc[o4].x);
            acc[o4].y = fmaf(vi, w.y, acc[o4].y);
            acc[o4].z = fmaf(vi, w.z, acc[o4].z);
            acc[o4].w = fmaf(vi, w.w, acc[o4].w);
        }
    }

    float* xo = g_x + m*GC + g*CAGG;
    #pragma unroll
    for (int o4 = 0; o4 < 8; ++o4) {
        float4 r;
        r.x = fmaxf(fmaf(acc[o4].x, ssc[o4*4+0], ssh[o4*4+0]), 0.0f);
        r.y = fmaxf(fmaf(acc[o4].y, ssc[o4*4+1], ssh[o4*4+1]), 0.0f);
        r.z = fmaxf(fmaf(acc[o4].z, ssc[o4*4+2], ssh[o4*4+2]), 0.0f);
        r.w = fmaxf(fmaf(acc[o4].w, ssc[o4*4+3], ssh[o4*4+3]), 0.0f);
        *(float4*)(xo + o4*4) = r;
    }
}

// ---------------------------------------------------------------------------
// K_post: split-K GEMM partials. CTA tile 64m x 128n, k=96 per split.
// block 128 (tx 0..15 over n, ty 0..7 over m), thread tile 8x8.
// smem k-major; pitches 68 / 132 (multiple of 4 -> aligned float4 reads).
// ---------------------------------------------------------------------------
__global__ __launch_bounds__(128) void k_post(const float* __restrict__ wp) {
    __shared__ float sA[32][68];
    __shared__ float sB[32][132];
    const int tid = threadIdx.x;
    const int tx = tid & 15;
    const int ty = tid >> 4;
    const int m0 = blockIdx.x * 64;
    const int kb0 = blockIdx.y * 96;

    float acc[8][8];
    #pragma unroll
    for (int i = 0; i < 8; ++i)
        #pragma unroll
        for (int j = 0; j < 8; ++j) acc[i][j] = 0.0f;

    for (int kc = 0; kc < 96; kc += 32) {
        const int kb = kb0 + kc;
        #pragma unroll
        for (int i = 0; i < 4; ++i) {               // A: 64m x 32k
            int f = tid + i*128;
            int mm = f >> 3, kq = (f & 7) << 2;
            float4 vv = *(const float4*)(g_x + (m0+mm)*GC + kb + kq);
            sA[kq+0][mm] = vv.x; sA[kq+1][mm] = vv.y;
            sA[kq+2][mm] = vv.z; sA[kq+3][mm] = vv.w;
        }
        #pragma unroll
        for (int i = 0; i < 8; ++i) {               // B: 128n x 32k
            int f = tid + i*128;
            int nr = f >> 3, kq = (f & 7) << 2;
            float4 vv = *(const float4*)(wp + nr*GC + kb + kq);
            sB[kq+0][nr] = vv.x; sB[kq+1][nr] = vv.y;
            sB[kq+2][nr] = vv.z; sB[kq+3][nr] = vv.w;
        }
        __syncthreads();
        #pragma unroll
        for (int k = 0; k < 32; ++k) {
            float av[8], bv[8];
            *(float4*)&av[0] = *(const float4*)&sA[k][ty*8];
            *(float4*)&av[4] = *(const float4*)&sA[k][ty*8 + 4];
            *(float4*)&bv[0] = *(const float4*)&sB[k][tx*4];
            *(float4*)&bv[4] = *(const float4*)&sB[k][64 + tx*4];
            #pragma unroll
            for (int i = 0; i < 8; ++i)
                #pragma unroll
                for (int j = 0; j < 8; ++j)
                    acc[i][j] = fmaf(av[i], bv[j], acc[i][j]);
        }
        __syncthreads();
    }

    float* dst = g_part[blockIdx.y];
    #pragma unroll
    for (int i = 0; i < 8; ++i) {
        int mrow = m0 + ty*8 + i;
        *(float4*)(dst + mrow*CPOST + tx*4)      = *(float4*)&acc[i][0];
        *(float4*)(dst + mrow*CPOST + 64 + tx*4) = *(float4*)&acc[i][4];
    }
}

// ---------------------------------------------------------------------------
// K_fin: sum split-K partials + BN2 + ReLU
// ---------------------------------------------------------------------------
__global__ void k_fin(const float* __restrict__ g2, const float* __restrict__ b2,
                      const float* __restrict__ mu2, const float* __restrict__ v2,
                      float* __restrict__ out) {
    int t = blockIdx.x * 256 + threadIdx.x;
    if (t >= BM*CPOST) return;
    int c = t & 127;
    float s = 0.0f;
    #pragma unroll
    for (int k = 0; k < KSPLIT; ++k) s += g_part[k][t];
    float scale = g2[c] * rsqrtf(v2[c] + 1e-5f);
    float shift = b2[c] - mu2[c]*scale;
    out[t] = fmaxf(fmaf(s, scale, shift), 0.0f);
}

// ---------------------------------------------------------------------------
extern "C" void kernel_launch(void* const* d_in, const int* in_sizes, int n_in,
                              void* d_out, int out_size) {
    const float* sxyz  = (const float*)d_in[0];
    const float* sfeat = (const float*)d_in[1];
    const float* nxyz  = (const float*)d_in[2];
    const float* wg    = (const float*)d_in[3];
    const float* g1    = (const float*)d_in[4];
    const float* b1    = (const float*)d_in[5];
    const float* m1    = (const float*)d_in[6];
    const float* v1    = (const float*)d_in[7];
    const float* wp    = (const float*)d_in[8];
    const float* g2    = (const float*)d_in[9];
    const float* b2    = (const float*)d_in[10];
    const float* m2    = (const float*)d_in[11];
    const float* v2    = (const float*)d_in[12];
    float* out = (float*)d_out;

    k_bin<<<BB, 256>>>(sxyz);
    k_reduce<<<(BB*NN*32 + 255)/256, 256>>>(sfeat);
    k_nn<<<NCENT/16, 256>>>(nxyz);
    k_group<<<dim3(BM/128, GG), 128>>>(wg, g1, b1, m1, v1);
    k_post<<<dim3(BM/64, KSPLIT), 128>>>(wp);
    k_fin<<<(BM*CPOST + 255)/256, 256>>>(g2, b2, m2, v2, out);
}

// round 8
// speedup vs baseline: 1.5988x; 1.0284x over previous
#include <cuda_runtime.h>
#include <math_constants.h>

#define BB 2
#define NN 2048
#define MM 512
#define GG 27
#define CAGG 32
#define CPOST 128
#define GC (GG*CAGG)      // 864
#define BM (BB*MM)        // 1024
#define NCENT (BM*GG)     // 27648
#define NCELL 512         // 8^3 grid
#define HCELL 1.25f
#define INVH 0.8f
#define KSPLIT 9

// Scratch (device globals; allocation is forbidden)
__device__ __align__(16) float4 g_pts4[BB][NN];          // binned points
__device__ int   g_cstart[BB][NCELL+1];
__device__ int   g_perm[BB][NN];
__device__ __align__(16) float g_feats[BB*NN*32];        // binned reduced feats
__device__ __align__(16) float g_wT[GG*41*CAGG];         // weights [g][i][o]
__device__ __align__(16) float g_sc1[GC], g_sh1[GC];     // folded BN1
__device__ __align__(16) float g_x[BM*GC];               // grouped-conv out
__device__ __align__(16) float g_part[KSPLIT][BM*CPOST]; // split-K partials

// ---------------------------------------------------------------------------
// K_wt: transpose grouped weights to [g][i][o]; fold BN1 into scale/shift
// ---------------------------------------------------------------------------
__global__ void k_wt(const float* __restrict__ wg, const float* __restrict__ g1,
                     const float* __restrict__ b1, const float* __restrict__ mu1,
                     const float* __restrict__ v1) {
    int t = blockIdx.x * 256 + threadIdx.x;
    if (t < GG*41*CAGG) {
        int g = t / (41*CAGG);
        int rm = t - g*(41*CAGG);
        int i = rm >> 5, o = rm & 31;
        g_wT[t] = wg[g*(CAGG*41) + o*41 + i];
    }
    if (t < GC) {
        float sc = g1[t] * rsqrtf(v1[t] + 1e-5f);
        g_sc1[t] = sc;
        g_sh1[t] = b1[t] - mu1[t]*sc;
    }
}

// ---------------------------------------------------------------------------
// K_bin: per-batch counting sort of support points into 8^3 cells
// ---------------------------------------------------------------------------
__global__ __launch_bounds__(256) void k_bin(const float* __restrict__ sxyz) {
    __shared__ int cnt[NCELL];
    __shared__ int start[NCELL+1];
    const int b = blockIdx.x;
    const int tid = threadIdx.x;
    for (int c = tid; c < NCELL; c += 256) cnt[c] = 0;
    __syncthreads();
    for (int p = tid; p < NN; p += 256) {
        const float* s = sxyz + (b*NN + p)*3;
        int cx = min(max((int)floorf(s[0]*INVH), 0), 7);
        int cy = min(max((int)floorf(s[1]*INVH), 0), 7);
        int cz = min(max((int)floorf(s[2]*INVH), 0), 7);
        atomicAdd(&cnt[(cx*8+cy)*8+cz], 1);
    }
    __syncthreads();
    if (tid < 32) {
        int base = tid*16, s = 0;
        #pragma unroll
        for (int i = 0; i < 16; ++i) s += cnt[base+i];
        int inc = s;
        #pragma unroll
        for (int o = 1; o < 32; o <<= 1) {
            int v = __shfl_up_sync(0xffffffffu, inc, o);
            if (tid >= o) inc += v;
        }
        int run = inc - s;
        #pragma unroll
        for (int i = 0; i < 16; ++i) { start[base+i] = run; run += cnt[base+i]; }
        if (tid == 31) start[NCELL] = run;
    }
    __syncthreads();
    for (int c = tid; c < NCELL; c += 256) cnt[c] = start[c];
    __syncthreads();
    for (int p = tid; p < NN; p += 256) {
        const float* s = sxyz + (b*NN + p)*3;
        float x = s[0], y = s[1], z = s[2];
        int cx = min(max((int)floorf(x*INVH), 0), 7);
        int cy = min(max((int)floorf(y*INVH), 0), 7);
        int cz = min(max((int)floorf(z*INVH), 0), 7);
        int pos = atomicAdd(&cnt[(cx*8+cy)*8+cz], 1);
        g_pts4[b][pos] = make_float4(x, y, z, 0.0f);
        g_perm[b][pos] = p;
    }
    for (int c = tid; c <= NCELL; c += 256) g_cstart[b][c] = start[c];
}

// ---------------------------------------------------------------------------
// K_reduce: channel reduction 128->32 gathered into binned order
// ---------------------------------------------------------------------------
__global__ void k_reduce(const float* __restrict__ sf) {
    int t = blockIdx.x * 256 + threadIdx.x;
    if (t >= BB*NN*32) return;
    int row = t >> 5, c = t & 31;
    int b = row / NN, p = row - b*NN;
    int orig = g_perm[b][p];
    const float* q = sf + (b*NN + orig)*128 + c;
    g_feats[t] = q[0] + q[32] + q[64] + q[96];
}

// Branchless insert of (d,i) into sorted triple d0<=d1<=d2
__device__ __forceinline__ void ins3(float d, int i,
        float& d0, int& i0, float& d1, int& i1, float& d2, int& i2) {
    bool c2 = d < d2, c1 = d < d1, c0 = d < d0;
    d2 = c1 ? d1 : (c2 ? d : d2);  i2 = c1 ? i1 : (c2 ? i : i2);
    d1 = c0 ? d0 : (c1 ? d : d1);  i1 = c0 ? i0 : (c1 ? i : i1);
    d0 = c0 ? d  : d0;             i0 = c0 ? i  : i0;
}

// ---------------------------------------------------------------------------
// K_nn: grid 3-NN per center (16-lane groups) + interp + FUSED grouped conv
// + BN1 + ReLU. Writes g_x directly. block 256 = 16 groups; grid NCENT/16.
// ---------------------------------------------------------------------------
__global__ __launch_bounds__(256) void k_nn(const float* __restrict__ nxyz) {
    __shared__ __align__(16) float sv[16][48];   // staged vec[41] per group
    __shared__ int cst[NCELL+1];
    const int tid = threadIdx.x;
    const int grp = tid >> 4;
    const int l   = tid & 15;
    const unsigned gmask = 0xffffu << (tid & 16);   // group-local shuffle mask
    const int cid = blockIdx.x*16 + grp;
    const int b   = (blockIdx.x*16) / (MM*GG);   // never straddles batches

    for (int i = tid; i < NCELL+1; i += 256) cst[i] = g_cstart[b][i];
    __syncthreads();

    const int m = cid / GG, g = cid - m*GG;
    const int ixg = g / 9;
    const int iyg = (g - ixg*9) / 3;
    const int izg = g - ixg*9 - iyg*3;
    const float cx = nxyz[m*3+0] + __fadd_rn(__fmul_rn((float)ixg + 0.5f, 1.6f), -2.4f);
    const float cy = nxyz[m*3+1] + __fadd_rn(__fmul_rn((float)iyg + 0.5f, 1.6f), -2.4f);
    const float cz = nxyz[m*3+2] + __fadd_rn(__fmul_rn((float)izg + 0.5f, 1.6f), -2.4f);
    const int icx = (int)floorf(cx * INVH);
    const int icy = (int)floorf(cy * INVH);
    const int icz = (int)floorf(cz * INVH);

    const float INF = CUDART_INF_F;
    float d0 = INF, d1 = INF, d2v = INF;   // per-lane (disjoint point sets)
    int   i0 = -1,  i1 = -1,  i2 = -1;
    float td0, td1, td2; int ti0, ti1, ti2;

    const float4* __restrict__ pts = g_pts4[b];

    for (int r = 1; r <= 4; ++r) {
        if (r == 1) {
            for (int c = l; c < 27; c += 16) {
                int x = icx + c/9 - 1;
                int y = icy + (c/3)%3 - 1;
                int z = icz + c%3 - 1;
                if (x < 0 || x > 7 || y < 0 || y > 7 || z < 0 || z > 7) continue;
                int cell = (x*8 + y)*8 + z;
                int s = cst[cell], e = cst[cell+1];
                for (int j = s; j < e; ++j) {
                    float4 p = __ldg(&pts[j]);
                    float dx = cx - p.x, dy = cy - p.y, dz = cz - p.z;
                    float dsq = fmaf(dx, dx, fmaf(dy, dy, dz*dz));
                    float ch  = fmaxf(fabsf(dx), fmaxf(fabsf(dy), fabsf(dz)));
                    float dd  = (ch <= 4.8f) ? dsq : INF;
                    ins3(dd, j, d0, i0, d1, i1, d2v, i2);
                }
            }
        } else {
            int side = 2*r + 1, s2 = side*side, tot = side*s2;
            for (int t = l; t < tot; t += 16) {
                int q  = t / s2;
                int rm = t - q*s2;
                int dxc = q - r, dyc = rm/side - r, dzc = rm - (rm/side)*side - r;
                if (abs(dxc) < r && abs(dyc) < r && abs(dzc) < r) continue;
                int x = icx + dxc, y = icy + dyc, z = icz + dzc;
                if (x < 0 || x > 7 || y < 0 || y > 7 || z < 0 || z > 7) continue;
                int cell = (x*8 + y)*8 + z;
                int s = cst[cell], e = cst[cell+1];
                for (int j = s; j < e; ++j) {
                    float4 p = __ldg(&pts[j]);
                    float dx = cx - p.x, dy = cy - p.y, dz = cz - p.z;
                    float dsq = fmaf(dx, dx, fmaf(dy, dy, dz*dz));
                    float ch  = fmaxf(fabsf(dx), fmaxf(fabsf(dy), fabsf(dz)));
                    float dd  = (ch <= 4.8f) ? dsq : INF;
                    ins3(dd, j, d0, i0, d1, i1, d2v, i2);
                }
            }
        }
        // merge into temps with GROUP-LOCAL mask (loop break is per-group)
        td0 = d0; td1 = d1; td2 = d2v; ti0 = i0; ti1 = i1; ti2 = i2;
        #pragma unroll
        for (int s = 1; s < 16; s <<= 1) {
            float e0 = __shfl_xor_sync(gmask, td0, s);
            int   j0 = __shfl_xor_sync(gmask, ti0, s);
            float e1 = __shfl_xor_sync(gmask, td1, s);
            int   j1 = __shfl_xor_sync(gmask, ti1, s);
            float e2 = __shfl_xor_sync(gmask, td2, s);
            int   j2 = __shfl_xor_sync(gmask, ti2, s);
            ins3(e0, j0, td0, ti0, td1, ti1, td2, ti2);
            ins3(e1, j1, td0, ti0, td1, ti1, td2, ti2);
            ins3(e2, j2, td0, ti0, td1, ti1, td2, ti2);
        }
        float bound = (float)r * HCELL - 1e-3f;
        if (td2 <= bound*bound) break;
    }

    const bool empty = !(td0 < INF);
    float r0 = (td0 < INF) ? 1.0f/(td0 + 1e-8f) : 0.0f;
    float r1 = (td1 < INF) ? 1.0f/(td1 + 1e-8f) : 0.0f;
    float r2 = (td2 < INF) ? 1.0f/(td2 + 1e-8f) : 0.0f;
    float ssum = fmaxf(r0 + r1 + r2, 1e-8f);
    float w0 = r0/ssum, w1 = r1/ssum, w2 = r2/ssum;
    if (ti0 < 0) ti0 = 0;
    if (ti1 < 0) ti1 = ti0;
    if (ti2 < 0) ti2 = ti0;

    // interp: lane handles 2 feature channels (float2) -> stage to smem
    {
        const float2* F0 = (const float2*)(g_feats + (b*NN + ti0)*32);
        const float2* F1 = (const float2*)(g_feats + (b*NN + ti1)*32);
        const float2* F2 = (const float2*)(g_feats + (b*NN + ti2)*32);
        float2 a = __ldg(&F0[l]), u = __ldg(&F1[l]), v = __ldg(&F2[l]);
        float2 f;
        f.x = empty ? 0.0f : (w0*a.x + w1*u.x + w2*v.x);
        f.y = empty ? 0.0f : (w0*a.y + w1*u.y + w2*v.y);
        ((float2*)sv[grp])[l] = f;
        if (l < 3) {
            int isel = (l == 0) ? ti0 : ((l == 1) ? ti1 : ti2);
            float4 p = __ldg(&pts[isel]);
            sv[grp][32 + l*3 + 0] = empty ? 0.0f : (cx - p.x);
            sv[grp][32 + l*3 + 1] = empty ? 0.0f : (cy - p.y);
            sv[grp][32 + l*3 + 2] = empty ? 0.0f : (cz - p.z);
        }
    }
    __syncwarp();

    // fused grouped conv: lane computes output channels 2l, 2l+1
    const float* wrow = g_wT + g*(41*CAGG) + 2*l;
    float a0 = 0.0f, a1 = 0.0f;
    #pragma unroll
    for (int i = 0; i < 41; ++i) {
        float vi = sv[grp][i];
        float2 w = *(const float2*)(wrow + i*CAGG);
        a0 = fmaf(vi, w.x, a0);
        a1 = fmaf(vi, w.y, a1);
    }
    const int gc = g*CAGG + 2*l;
    float2 r;
    r.x = fmaxf(fmaf(a0, __ldg(&g_sc1[gc]),   __ldg(&g_sh1[gc])),   0.0f);
    r.y = fmaxf(fmaf(a1, __ldg(&g_sc1[gc+1]), __ldg(&g_sh1[gc+1])), 0.0f);
    *(float2*)(g_x + m*GC + gc) = r;
}

// ---------------------------------------------------------------------------
// K_post: split-K GEMM partials. CTA tile 64m x 128n, k=96 per split.
// block 128 (tx 0..15 over n, ty 0..7 over m), thread tile 8x8.
// smem k-major; pitches 68 / 132 (multiple of 4 -> aligned float4 reads).
// ---------------------------------------------------------------------------
__global__ __launch_bounds__(128) void k_post(const float* __restrict__ wp) {
    __shared__ float sA[32][68];
    __shared__ float sB[32][132];
    const int tid = threadIdx.x;
    const int tx = tid & 15;
    const int ty = tid >> 4;
    const int m0 = blockIdx.x * 64;
    const int kb0 = blockIdx.y * 96;

    float acc[8][8];
    #pragma unroll
    for (int i = 0; i < 8; ++i)
        #pragma unroll
        for (int j = 0; j < 8; ++j) acc[i][j] = 0.0f;

    for (int kc = 0; kc < 96; kc += 32) {
        const int kb = kb0 + kc;
        #pragma unroll
        for (int i = 0; i < 4; ++i) {               // A: 64m x 32k
            int f = tid + i*128;
            int mm = f >> 3, kq = (f & 7) << 2;
            float4 vv = *(const float4*)(g_x + (m0+mm)*GC + kb + kq);
            sA[kq+0][mm] = vv.x; sA[kq+1][mm] = vv.y;
            sA[kq+2][mm] = vv.z; sA[kq+3][mm] = vv.w;
        }
        #pragma unroll
        for (int i = 0; i < 8; ++i) {               // B: 128n x 32k
            int f = tid + i*128;
            int nr = f >> 3, kq = (f & 7) << 2;
            float4 vv = *(const float4*)(wp + nr*GC + kb + kq);
            sB[kq+0][nr] = vv.x; sB[kq+1][nr] = vv.y;
            sB[kq+2][nr] = vv.z; sB[kq+3][nr] = vv.w;
        }
        __syncthreads();
        #pragma unroll
        for (int k = 0; k < 32; ++k) {
            float av[8], bv[8];
            *(float4*)&av[0] = *(const float4*)&sA[k][ty*8];
            *(float4*)&av[4] = *(const float4*)&sA[k][ty*8 + 4];
            *(float4*)&bv[0] = *(const float4*)&sB[k][tx*4];
            *(float4*)&bv[4] = *(const float4*)&sB[k][64 + tx*4];
            #pragma unroll
            for (int i = 0; i < 8; ++i)
                #pragma unroll
                for (int j = 0; j < 8; ++j)
                    acc[i][j] = fmaf(av[i], bv[j], acc[i][j]);
        }
        __syncthreads();
    }

    float* dst = g_part[blockIdx.y];
    #pragma unroll
    for (int i = 0; i < 8; ++i) {
        int mrow = m0 + ty*8 + i;
        *(float4*)(dst + mrow*CPOST + tx*4)      = *(float4*)&acc[i][0];
        *(float4*)(dst + mrow*CPOST + 64 + tx*4) = *(float4*)&acc[i][4];
    }
}

// ---------------------------------------------------------------------------
// K_fin: sum split-K partials + BN2 + ReLU
// ---------------------------------------------------------------------------
__global__ void k_fin(const float* __restrict__ g2, const float* __restrict__ b2,
                      const float* __restrict__ mu2, const float* __restrict__ v2,
                      float* __restrict__ out) {
    int t = blockIdx.x * 256 + threadIdx.x;
    if (t >= BM*CPOST) return;
    int c = t & 127;
    float s = 0.0f;
    #pragma unroll
    for (int k = 0; k < KSPLIT; ++k) s += g_part[k][t];
    float scale = g2[c] * rsqrtf(v2[c] + 1e-5f);
    float shift = b2[c] - mu2[c]*scale;
    out[t] = fmaxf(fmaf(s, scale, shift), 0.0f);
}

// ---------------------------------------------------------------------------
extern "C" void kernel_launch(void* const* d_in, const int* in_sizes, int n_in,
                              void* d_out, int out_size) {
    const float* sxyz  = (const float*)d_in[0];
    const float* sfeat = (const float*)d_in[1];
    const float* nxyz  = (const float*)d_in[2];
    const float* wg    = (const float*)d_in[3];
    const float* g1    = (const float*)d_in[4];
    const float* b1    = (const float*)d_in[5];
    const float* m1    = (const float*)d_in[6];
    const float* v1    = (const float*)d_in[7];
    const float* wp    = (const float*)d_in[8];
    const float* g2    = (const float*)d_in[9];
    const float* b2    = (const float*)d_in[10];
    const float* m2    = (const float*)d_in[11];
    const float* v2    = (const float*)d_in[12];
    float* out = (float*)d_out;

    k_wt<<<(GG*41*CAGG + 255)/256, 256>>>(wg, g1, b1, m1, v1);
    k_bin<<<BB, 256>>>(sxyz);
    k_reduce<<<(BB*NN*32 + 255)/256, 256>>>(sfeat);
    k_nn<<<NCENT/16, 256>>>(nxyz);
    k_post<<<dim3(BM/64, KSPLIT), 128>>>(wp);
    k_fin<<<(BM*CPOST + 255)/256, 256>>>(g2, b2, m2, v2, out);
}

// round 9
// speedup vs baseline: 1.6463x; 1.0297x over previous
#include <cuda_runtime.h>
#include <math_constants.h>

#define BB 2
#define NN 2048
#define MM 512
#define GG 27
#define CAGG 32
#define CPOST 128
#define GC (GG*CAGG)      // 864
#define BM (BB*MM)        // 1024
#define NCENT (BM*GG)     // 27648
#define NCELL 512         // 8^3 grid
#define HCELL 1.25f
#define INVH 0.8f
#define KSPLIT 9

// Scratch (device globals; allocation is forbidden)
__device__ __align__(16) float4 g_pts4[BB][NN];          // binned points
__device__ int   g_cstart[BB][NCELL+1];
__device__ int   g_perm[BB][NN];
__device__ __align__(16) float g_feats[BB*NN*32];        // binned reduced feats
__device__ __align__(16) float g_wT[GG*41*CAGG];         // weights [g][i][o]
__device__ __align__(16) float g_sc1[GC], g_sh1[GC];     // folded BN1
__device__ __align__(16) float g_x[BM*GC];               // grouped-conv out
__device__ __align__(16) float g_part[KSPLIT][BM*CPOST]; // split-K partials

// ---------------------------------------------------------------------------
// K_wt: transpose grouped weights to [g][i][o]; fold BN1 into scale/shift
// ---------------------------------------------------------------------------
__global__ void k_wt(const float* __restrict__ wg, const float* __restrict__ g1,
                     const float* __restrict__ b1, const float* __restrict__ mu1,
                     const float* __restrict__ v1) {
    int t = blockIdx.x * 256 + threadIdx.x;
    if (t < GG*41*CAGG) {
        int g = t / (41*CAGG);
        int rm = t - g*(41*CAGG);
        int i = rm >> 5, o = rm & 31;
        g_wT[t] = wg[g*(CAGG*41) + o*41 + i];
    }
    if (t < GC) {
        float sc = g1[t] * rsqrtf(v1[t] + 1e-5f);
        g_sc1[t] = sc;
        g_sh1[t] = b1[t] - mu1[t]*sc;
    }
}

// ---------------------------------------------------------------------------
// K_bin: per-batch counting sort of support points into 8^3 cells
// ---------------------------------------------------------------------------
__global__ __launch_bounds__(256) void k_bin(const float* __restrict__ sxyz) {
    __shared__ int cnt[NCELL];
    __shared__ int start[NCELL+1];
    const int b = blockIdx.x;
    const int tid = threadIdx.x;
    for (int c = tid; c < NCELL; c += 256) cnt[c] = 0;
    __syncthreads();
    for (int p = tid; p < NN; p += 256) {
        const float* s = sxyz + (b*NN + p)*3;
        int cx = min(max((int)floorf(s[0]*INVH), 0), 7);
        int cy = min(max((int)floorf(s[1]*INVH), 0), 7);
        int cz = min(max((int)floorf(s[2]*INVH), 0), 7);
        atomicAdd(&cnt[(cx*8+cy)*8+cz], 1);
    }
    __syncthreads();
    if (tid < 32) {
        int base = tid*16, s = 0;
        #pragma unroll
        for (int i = 0; i < 16; ++i) s += cnt[base+i];
        int inc = s;
        #pragma unroll
        for (int o = 1; o < 32; o <<= 1) {
            int v = __shfl_up_sync(0xffffffffu, inc, o);
            if (tid >= o) inc += v;
        }
        int run = inc - s;
        #pragma unroll
        for (int i = 0; i < 16; ++i) { start[base+i] = run; run += cnt[base+i]; }
        if (tid == 31) start[NCELL] = run;
    }
    __syncthreads();
    for (int c = tid; c < NCELL; c += 256) cnt[c] = start[c];
    __syncthreads();
    for (int p = tid; p < NN; p += 256) {
        const float* s = sxyz + (b*NN + p)*3;
        float x = s[0], y = s[1], z = s[2];
        int cx = min(max((int)floorf(x*INVH), 0), 7);
        int cy = min(max((int)floorf(y*INVH), 0), 7);
        int cz = min(max((int)floorf(z*INVH), 0), 7);
        int pos = atomicAdd(&cnt[(cx*8+cy)*8+cz], 1);
        g_pts4[b][pos] = make_float4(x, y, z, 0.0f);
        g_perm[b][pos] = p;
    }
    for (int c = tid; c <= NCELL; c += 256) g_cstart[b][c] = start[c];
}

// ---------------------------------------------------------------------------
// K_reduce: channel reduction 128->32 gathered into binned order
// ---------------------------------------------------------------------------
__global__ void k_reduce(const float* __restrict__ sf) {
    int t = blockIdx.x * 256 + threadIdx.x;
    if (t >= BB*NN*32) return;
    int row = t >> 5, c = t & 31;
    int b = row / NN, p = row - b*NN;
    int orig = g_perm[b][p];
    const float* q = sf + (b*NN + orig)*128 + c;
    g_feats[t] = q[0] + q[32] + q[64] + q[96];
}

// Branchless insert of (d,i) into sorted triple d0<=d1<=d2
__device__ __forceinline__ void ins3(float d, int i,
        float& d0, int& i0, float& d1, int& i1, float& d2, int& i2) {
    bool c2 = d < d2, c1 = d < d1, c0 = d < d0;
    d2 = c1 ? d1 : (c2 ? d : d2);  i2 = c1 ? i1 : (c2 ? i : i2);
    d1 = c0 ? d0 : (c1 ? d : d1);  i1 = c0 ? i0 : (c1 ? i : i1);
    d0 = c0 ? d  : d0;             i0 = c0 ? i  : i0;
}

// ---------------------------------------------------------------------------
// K_nn: grid 3-NN per center (16-lane groups) + interp + FUSED grouped conv
// + BN1 + ReLU. r=1 box scanned as <=9 CONTIGUOUS z-runs (lanes stride points
// within a run -> convergent). Writes g_x directly.
// ---------------------------------------------------------------------------
__global__ __launch_bounds__(256) void k_nn(const float* __restrict__ nxyz) {
    __shared__ __align__(16) float sv[16][48];   // staged vec[41] per group
    __shared__ int cst[NCELL+1];
    const int tid = threadIdx.x;
    const int grp = tid >> 4;
    const int l   = tid & 15;
    const unsigned gmask = 0xffffu << (tid & 16);   // group-local shuffle mask
    const int cid = blockIdx.x*16 + grp;
    const int b   = (blockIdx.x*16) / (MM*GG);   // never straddles batches

    for (int i = tid; i < NCELL+1; i += 256) cst[i] = g_cstart[b][i];
    __syncthreads();

    const int m = cid / GG, g = cid - m*GG;
    const int ixg = g / 9;
    const int iyg = (g - ixg*9) / 3;
    const int izg = g - ixg*9 - iyg*3;
    const float cx = nxyz[m*3+0] + __fadd_rn(__fmul_rn((float)ixg + 0.5f, 1.6f), -2.4f);
    const float cy = nxyz[m*3+1] + __fadd_rn(__fmul_rn((float)iyg + 0.5f, 1.6f), -2.4f);
    const float cz = nxyz[m*3+2] + __fadd_rn(__fmul_rn((float)izg + 0.5f, 1.6f), -2.4f);
    const int icx = (int)floorf(cx * INVH);
    const int icy = (int)floorf(cy * INVH);
    const int icz = (int)floorf(cz * INVH);

    const float INF = CUDART_INF_F;
    float d0 = INF, d1 = INF, d2v = INF;   // per-lane (disjoint point sets)
    int   i0 = -1,  i1 = -1,  i2 = -1;
    float td0, td1, td2; int ti0, ti1, ti2;

    const float4* __restrict__ pts = g_pts4[b];

    // ---- r=1: 3x3x3 box as contiguous z-runs; lanes stride points in a run
    {
        const int xlo = max(icx-1, 0), xhi = min(icx+1, 7);
        const int ylo = max(icy-1, 0), yhi = min(icy+1, 7);
        const int zlo = max(icz-1, 0), zhi = min(icz+1, 7);
        for (int x = xlo; x <= xhi; ++x)
        for (int y = ylo; y <= yhi; ++y) {
            const int base = (x*8 + y)*8;
            const int s = cst[base + zlo], e = cst[base + zhi + 1];
            for (int j = s + l; j < e; j += 16) {
                float4 p = __ldg(&pts[j]);
                float dx = cx - p.x, dy = cy - p.y, dz = cz - p.z;
                float dsq = fmaf(dx, dx, fmaf(dy, dy, dz*dz));
                float ch  = fmaxf(fabsf(dx), fmaxf(fabsf(dy), fabsf(dz)));
                float dd  = (ch <= 4.8f) ? dsq : INF;
                ins3(dd, j, d0, i0, d1, i1, d2v, i2);
            }
        }
        // merge (group-local mask: break decisions are per-group)
        td0 = d0; td1 = d1; td2 = d2v; ti0 = i0; ti1 = i1; ti2 = i2;
        #pragma unroll
        for (int s = 1; s < 16; s <<= 1) {
            float e0 = __shfl_xor_sync(gmask, td0, s);
            int   j0 = __shfl_xor_sync(gmask, ti0, s);
            float e1 = __shfl_xor_sync(gmask, td1, s);
            int   j1 = __shfl_xor_sync(gmask, ti1, s);
            float e2 = __shfl_xor_sync(gmask, td2, s);
            int   j2 = __shfl_xor_sync(gmask, ti2, s);
            ins3(e0, j0, td0, ti0, td1, ti1, td2, ti2);
            ins3(e1, j1, td0, ti0, td1, ti1, td2, ti2);
            ins3(e2, j2, td0, ti0, td1, ti1, td2, ti2);
        }
    }

    // ---- rare expansion: shells r=2..4 (old path)
    {
        float bound1 = HCELL - 1e-3f;
        if (!(td2 <= bound1*bound1)) {
            for (int r = 2; r <= 4; ++r) {
                int side = 2*r + 1, s2 = side*side, tot = side*s2;
                for (int t = l; t < tot; t += 16) {
                    int q  = t / s2;
                    int rm = t - q*s2;
                    int dxc = q - r, dyc = rm/side - r, dzc = rm - (rm/side)*side - r;
                    if (abs(dxc) < r && abs(dyc) < r && abs(dzc) < r) continue;
                    int x = icx + dxc, y = icy + dyc, z = icz + dzc;
                    if (x < 0 || x > 7 || y < 0 || y > 7 || z < 0 || z > 7) continue;
                    int cell = (x*8 + y)*8 + z;
                    int s = cst[cell], e = cst[cell+1];
                    for (int j = s; j < e; ++j) {
                        float4 p = __ldg(&pts[j]);
                        float dx = cx - p.x, dy = cy - p.y, dz = cz - p.z;
                        float dsq = fmaf(dx, dx, fmaf(dy, dy, dz*dz));
                        float ch  = fmaxf(fabsf(dx), fmaxf(fabsf(dy), fabsf(dz)));
                        float dd  = (ch <= 4.8f) ? dsq : INF;
                        ins3(dd, j, d0, i0, d1, i1, d2v, i2);
                    }
                }
                td0 = d0; td1 = d1; td2 = d2v; ti0 = i0; ti1 = i1; ti2 = i2;
                #pragma unroll
                for (int s = 1; s < 16; s <<= 1) {
                    float e0 = __shfl_xor_sync(gmask, td0, s);
                    int   j0 = __shfl_xor_sync(gmask, ti0, s);
                    float e1 = __shfl_xor_sync(gmask, td1, s);
                    int   j1 = __shfl_xor_sync(gmask, ti1, s);
                    float e2 = __shfl_xor_sync(gmask, td2, s);
                    int   j2 = __shfl_xor_sync(gmask, ti2, s);
                    ins3(e0, j0, td0, ti0, td1, ti1, td2, ti2);
                    ins3(e1, j1, td0, ti0, td1, ti1, td2, ti2);
                    ins3(e2, j2, td0, ti0, td1, ti1, td2, ti2);
                }
                float bound = (float)r * HCELL - 1e-3f;
                if (td2 <= bound*bound) break;
            }
        }
    }

    const bool empty = !(td0 < INF);
    float r0 = (td0 < INF) ? 1.0f/(td0 + 1e-8f) : 0.0f;
    float r1 = (td1 < INF) ? 1.0f/(td1 + 1e-8f) : 0.0f;
    float r2 = (td2 < INF) ? 1.0f/(td2 + 1e-8f) : 0.0f;
    float ssum = fmaxf(r0 + r1 + r2, 1e-8f);
    float w0 = r0/ssum, w1 = r1/ssum, w2 = r2/ssum;
    if (ti0 < 0) ti0 = 0;
    if (ti1 < 0) ti1 = ti0;
    if (ti2 < 0) ti2 = ti0;

    // interp: lane handles 2 feature channels (float2) -> stage to smem
    {
        const float2* F0 = (const float2*)(g_feats + (b*NN + ti0)*32);
        const float2* F1 = (const float2*)(g_feats + (b*NN + ti1)*32);
        const float2* F2 = (const float2*)(g_feats + (b*NN + ti2)*32);
        float2 a = __ldg(&F0[l]), u = __ldg(&F1[l]), v = __ldg(&F2[l]);
        float2 f;
        f.x = empty ? 0.0f : (w0*a.x + w1*u.x + w2*v.x);
        f.y = empty ? 0.0f : (w0*a.y + w1*u.y + w2*v.y);
        ((float2*)sv[grp])[l] = f;
        if (l < 3) {
            int isel = (l == 0) ? ti0 : ((l == 1) ? ti1 : ti2);
            float4 p = __ldg(&pts[isel]);
            sv[grp][32 + l*3 + 0] = empty ? 0.0f : (cx - p.x);
            sv[grp][32 + l*3 + 1] = empty ? 0.0f : (cy - p.y);
            sv[grp][32 + l*3 + 2] = empty ? 0.0f : (cz - p.z);
        }
    }
    __syncwarp();

    // fused grouped conv: lane computes output channels 2l, 2l+1
    const float* wrow = g_wT + g*(41*CAGG) + 2*l;
    float a0 = 0.0f, a1 = 0.0f;
    #pragma unroll
    for (int i = 0; i < 41; ++i) {
        float vi = sv[grp][i];
        float2 w = *(const float2*)(wrow + i*CAGG);
        a0 = fmaf(vi, w.x, a0);
        a1 = fmaf(vi, w.y, a1);
    }
    const int gc = g*CAGG + 2*l;
    float2 r;
    r.x = fmaxf(fmaf(a0, __ldg(&g_sc1[gc]),   __ldg(&g_sh1[gc])),   0.0f);
    r.y = fmaxf(fmaf(a1, __ldg(&g_sc1[gc+1]), __ldg(&g_sh1[gc+1])), 0.0f);
    *(float2*)(g_x + m*GC + gc) = r;
}

// ---------------------------------------------------------------------------
// K_post: split-K GEMM partials. CTA tile 64m x 128n, k=96 per split.
// ---------------------------------------------------------------------------
__global__ __launch_bounds__(128) void k_post(const float* __restrict__ wp) {
    __shared__ float sA[32][68];
    __shared__ float sB[32][132];
    const int tid = threadIdx.x;
    const int tx = tid & 15;
    const int ty = tid >> 4;
    const int m0 = blockIdx.x * 64;
    const int kb0 = blockIdx.y * 96;

    float acc[8][8];
    #pragma unroll
    for (int i = 0; i < 8; ++i)
        #pragma unroll
        for (int j = 0; j < 8; ++j) acc[i][j] = 0.0f;

    for (int kc = 0; kc < 96; kc += 32) {
        const int kb = kb0 + kc;
        #pragma unroll
        for (int i = 0; i < 4; ++i) {               // A: 64m x 32k
            int f = tid + i*128;
            int mm = f >> 3, kq = (f & 7) << 2;
            float4 vv = *(const float4*)(g_x + (m0+mm)*GC + kb + kq);
            sA[kq+0][mm] = vv.x; sA[kq+1][mm] = vv.y;
            sA[kq+2][mm] = vv.z; sA[kq+3][mm] = vv.w;
        }
        #pragma unroll
        for (int i = 0; i < 8; ++i) {               // B: 128n x 32k
            int f = tid + i*128;
            int nr = f >> 3, kq = (f & 7) << 2;
            float4 vv = *(const float4*)(wp + nr*GC + kb + kq);
            sB[kq+0][nr] = vv.x; sB[kq+1][nr] = vv.y;
            sB[kq+2][nr] = vv.z; sB[kq+3][nr] = vv.w;
        }
        __syncthreads();
        #pragma unroll
        for (int k = 0; k < 32; ++k) {
            float av[8], bv[8];
            *(float4*)&av[0] = *(const float4*)&sA[k][ty*8];
            *(float4*)&av[4] = *(const float4*)&sA[k][ty*8 + 4];
            *(float4*)&bv[0] = *(const float4*)&sB[k][tx*4];
            *(float4*)&bv[4] = *(const float4*)&sB[k][64 + tx*4];
            #pragma unroll
            for (int i = 0; i < 8; ++i)
                #pragma unroll
                for (int j = 0; j < 8; ++j)
                    acc[i][j] = fmaf(av[i], bv[j], acc[i][j]);
        }
        __syncthreads();
    }

    float* dst = g_part[blockIdx.y];
    #pragma unroll
    for (int i = 0; i < 8; ++i) {
        int mrow = m0 + ty*8 + i;
        *(float4*)(dst + mrow*CPOST + tx*4)      = *(float4*)&acc[i][0];
        *(float4*)(dst + mrow*CPOST + 64 + tx*4) = *(float4*)&acc[i][4];
    }
}

// ---------------------------------------------------------------------------
// K_fin: sum split-K partials + BN2 + ReLU
// ---------------------------------------------------------------------------
__global__ void k_fin(const float* __restrict__ g2, const float* __restrict__ b2,
                      const float* __restrict__ mu2, const float* __restrict__ v2,
                      float* __restrict__ out) {
    int t = blockIdx.x * 256 + threadIdx.x;
    if (t >= BM*CPOST) return;
    int c = t & 127;
    float s = 0.0f;
    #pragma unroll
    for (int k = 0; k < KSPLIT; ++k) s += g_part[k][t];
    float scale = g2[c] * rsqrtf(v2[c] + 1e-5f);
    float shift = b2[c] - mu2[c]*scale;
    out[t] = fmaxf(fmaf(s, scale, shift), 0.0f);
}

// ---------------------------------------------------------------------------
extern "C" void kernel_launch(void* const* d_in, const int* in_sizes, int n_in,
                              void* d_out, int out_size) {
    const float* sxyz  = (const float*)d_in[0];
    const float* sfeat = (const float*)d_in[1];
    const float* nxyz  = (const float*)d_in[2];
    const float* wg    = (const float*)d_in[3];
    const float* g1    = (const float*)d_in[4];
    const float* b1    = (const float*)d_in[5];
    const float* m1    = (const float*)d_in[6];
    const float* v1    = (const float*)d_in[7];
    const float* wp    = (const float*)d_in[8];
    const float* g2    = (const float*)d_in[9];
    const float* b2    = (const float*)d_in[10];
    const float* m2    = (const float*)d_in[11];
    const float* v2    = (const float*)d_in[12];
    float* out = (float*)d_out;

    k_wt<<<(GG*41*CAGG + 255)/256, 256>>>(wg, g1, b1, m1, v1);
    k_bin<<<BB, 256>>>(sxyz);
    k_reduce<<<(BB*NN*32 + 255)/256, 256>>>(sfeat);
    k_nn<<<NCENT/16, 256>>>(nxyz);
    k_post<<<dim3(BM/64, KSPLIT), 128>>>(wp);
    k_fin<<<(BM*CPOST + 255)/256, 256>>>(g2, b2, m2, v2, out);
}

// round 10
// speedup vs baseline: 1.8574x; 1.1282x over previous
#include <cuda_runtime.h>
#include <math_constants.h>

#define BB 2
#define NN 2048
#define MM 512
#define GG 27
#define CAGG 32
#define CPOST 128
#define GC (GG*CAGG)      // 864
#define BM (BB*MM)        // 1024
#define NCENT (BM*GG)     // 27648
#define NCELL 512         // 8^3 grid
#define HCELL 1.25f
#define INVH 0.8f
#define KSPLIT 9

// Scratch (device globals; allocation is forbidden)
__device__ __align__(16) float4 g_pts4[BB][NN];          // binned points
__device__ int   g_cstart[BB][NCELL+1];
__device__ int   g_perm[BB][NN];
__device__ __align__(16) float g_feats[BB*NN*32];        // binned reduced feats
__device__ __align__(16) float g_wT[GG*41*CAGG];         // weights [g][i][o]
__device__ __align__(16) float g_sc1[GC], g_sh1[GC];     // folded BN1
__device__ __align__(16) float g_x[BM*GC];               // grouped-conv out
__device__ __align__(16) float g_part[KSPLIT][BM*CPOST]; // split-K partials

// ---------------------------------------------------------------------------
// K_wt: transpose grouped weights to [g][i][o]; fold BN1 into scale/shift
// ---------------------------------------------------------------------------
__global__ void k_wt(const float* __restrict__ wg, const float* __restrict__ g1,
                     const float* __restrict__ b1, const float* __restrict__ mu1,
                     const float* __restrict__ v1) {
    int t = blockIdx.x * 256 + threadIdx.x;
    if (t < GG*41*CAGG) {
        int g = t / (41*CAGG);
        int rm = t - g*(41*CAGG);
        int i = rm >> 5, o = rm & 31;
        g_wT[t] = wg[g*(CAGG*41) + o*41 + i];
    }
    if (t < GC) {
        float sc = g1[t] * rsqrtf(v1[t] + 1e-5f);
        g_sc1[t] = sc;
        g_sh1[t] = b1[t] - mu1[t]*sc;
    }
}

// ---------------------------------------------------------------------------
// K_bin: per-batch counting sort of support points into 8^3 cells
// ---------------------------------------------------------------------------
__global__ __launch_bounds__(256) void k_bin(const float* __restrict__ sxyz) {
    __shared__ int cnt[NCELL];
    __shared__ int start[NCELL+1];
    const int b = blockIdx.x;
    const int tid = threadIdx.x;
    for (int c = tid; c < NCELL; c += 256) cnt[c] = 0;
    __syncthreads();
    for (int p = tid; p < NN; p += 256) {
        const float* s = sxyz + (b*NN + p)*3;
        int cx = min(max((int)floorf(s[0]*INVH), 0), 7);
        int cy = min(max((int)floorf(s[1]*INVH), 0), 7);
        int cz = min(max((int)floorf(s[2]*INVH), 0), 7);
        atomicAdd(&cnt[(cx*8+cy)*8+cz], 1);
    }
    __syncthreads();
    if (tid < 32) {
        int base = tid*16, s = 0;
        #pragma unroll
        for (int i = 0; i < 16; ++i) s += cnt[base+i];
        int inc = s;
        #pragma unroll
        for (int o = 1; o < 32; o <<= 1) {
            int v = __shfl_up_sync(0xffffffffu, inc, o);
            if (tid >= o) inc += v;
        }
        int run = inc - s;
        #pragma unroll
        for (int i = 0; i < 16; ++i) { start[base+i] = run; run += cnt[base+i]; }
        if (tid == 31) start[NCELL] = run;
    }
    __syncthreads();
    for (int c = tid; c < NCELL; c += 256) cnt[c] = start[c];
    __syncthreads();
    for (int p = tid; p < NN; p += 256) {
        const float* s = sxyz + (b*NN + p)*3;
        float x = s[0], y = s[1], z = s[2];
        int cx = min(max((int)floorf(x*INVH), 0), 7);
        int cy = min(max((int)floorf(y*INVH), 0), 7);
        int cz = min(max((int)floorf(z*INVH), 0), 7);
        int pos = atomicAdd(&cnt[(cx*8+cy)*8+cz], 1);
        g_pts4[b][pos] = make_float4(x, y, z, 0.0f);
        g_perm[b][pos] = p;
    }
    for (int c = tid; c <= NCELL; c += 256) g_cstart[b][c] = start[c];
}

// ---------------------------------------------------------------------------
// K_reduce: channel reduction 128->32 gathered into binned order
// ---------------------------------------------------------------------------
__global__ void k_reduce(const float* __restrict__ sf) {
    int t = blockIdx.x * 256 + threadIdx.x;
    if (t >= BB*NN*32) return;
    int row = t >> 5, c = t & 31;
    int b = row / NN, p = row - b*NN;
    int orig = g_perm[b][p];
    const float* q = sf + (b*NN + orig)*128 + c;
    g_feats[t] = q[0] + q[32] + q[64] + q[96];
}

// Branchless insert of (d,i) into sorted triple d0<=d1<=d2
__device__ __forceinline__ void ins3(float d, int i,
        float& d0, int& i0, float& d1, int& i1, float& d2, int& i2) {
    bool c2 = d < d2, c1 = d < d1, c0 = d < d0;
    d2 = c1 ? d1 : (c2 ? d : d2);  i2 = c1 ? i1 : (c2 ? i : i2);
    d1 = c0 ? d0 : (c1 ? d : d1);  i1 = c0 ? i0 : (c1 ? i : i1);
    d0 = c0 ? d  : d0;             i0 = c0 ? i  : i0;
}

// ---------------------------------------------------------------------------
// K_nn: grid 3-NN per center (16-lane groups) + interp + FUSED grouped conv
// + BN1 + ReLU. Box-growing ring scan as contiguous z-runs; cheap count-based
// termination (redux), top-3 merge deferred to ONE pass. Writes g_x.
// ---------------------------------------------------------------------------
__global__ __launch_bounds__(256) void k_nn(const float* __restrict__ nxyz) {
    __shared__ __align__(16) float sv[16][48];   // staged vec[41] per group
    __shared__ int cst[NCELL+1];
    const int tid = threadIdx.x;
    const int grp = tid >> 4;
    const int l   = tid & 15;
    const unsigned gmask = 0xffffu << (tid & 16);   // group-local mask
    const int cid = blockIdx.x*16 + grp;
    const int b   = (blockIdx.x*16) / (MM*GG);   // never straddles batches

    for (int i = tid; i < NCELL+1; i += 256) cst[i] = g_cstart[b][i];
    __syncthreads();

    const int m = cid / GG, g = cid - m*GG;
    const int ixg = g / 9;
    const int iyg = (g - ixg*9) / 3;
    const int izg = g - ixg*9 - iyg*3;
    const float cx = nxyz[m*3+0] + __fadd_rn(__fmul_rn((float)ixg + 0.5f, 1.6f), -2.4f);
    const float cy = nxyz[m*3+1] + __fadd_rn(__fmul_rn((float)iyg + 0.5f, 1.6f), -2.4f);
    const float cz = nxyz[m*3+2] + __fadd_rn(__fmul_rn((float)izg + 0.5f, 1.6f), -2.4f);
    const int icx = (int)floorf(cx * INVH);
    const int icy = (int)floorf(cy * INVH);
    const int icz = (int)floorf(cz * INVH);

    const float INF = CUDART_INF_F;
    float d0 = INF, d1 = INF, d2v = INF;   // per-lane triple (disjoint sets)
    int   i0 = -1,  i1 = -1,  i2 = -1;

    const float4* __restrict__ pts = g_pts4[b];

    // box-growing scan; prev box tracked for ring = newbox \ prevbox
    int xlo = 1, xhi = 0, ylo = 1, yhi = 0, zlo = 1, zhi = 0;  // empty
    bool havePrev = false;

    for (int r = 1; r <= 10; ++r) {
        const int nxlo = max(icx-r, 0), nxhi = min(icx+r, 7);
        const int nylo = max(icy-r, 0), nyhi = min(icy+r, 7);
        const int nzlo = max(icz-r, 0), nzhi = min(icz+r, 7);
        const bool valid = (nxhi >= nxlo) && (nyhi >= nylo) && (nzhi >= nzlo);
        if (valid) {
            for (int x = nxlo; x <= nxhi; ++x)
            for (int y = nylo; y <= nyhi; ++y) {
                const int base = (x*8 + y)*8;
                const bool rowPrev = havePrev &&
                    x >= xlo && x <= xhi && y >= ylo && y <= yhi;
                int al, ah, bl, bh;
                if (rowPrev) { al = nzlo; ah = zlo-1; bl = zhi+1; bh = nzhi; }
                else         { al = nzlo; ah = nzhi;  bl = 1;     bh = 0;   }
                if (ah >= al) {
                    const int s = cst[base+al], e = cst[base+ah+1];
                    for (int j = s + l; j < e; j += 16) {
                        float4 p = __ldg(&pts[j]);
                        float dx = cx - p.x, dy = cy - p.y, dz = cz - p.z;
                        float dsq = fmaf(dx, dx, fmaf(dy, dy, dz*dz));
                        float ch  = fmaxf(fabsf(dx), fmaxf(fabsf(dy), fabsf(dz)));
                        float dd  = (ch <= 4.8f) ? dsq : INF;
                        ins3(dd, j, d0, i0, d1, i1, d2v, i2);
                    }
                }
                if (bh >= bl) {
                    const int s = cst[base+bl], e = cst[base+bh+1];
                    for (int j = s + l; j < e; j += 16) {
                        float4 p = __ldg(&pts[j]);
                        float dx = cx - p.x, dy = cy - p.y, dz = cz - p.z;
                        float dsq = fmaf(dx, dx, fmaf(dy, dy, dz*dz));
                        float ch  = fmaxf(fabsf(dx), fmaxf(fabsf(dy), fabsf(dz)));
                        float dd  = (ch <= 4.8f) ? dsq : INF;
                        ins3(dd, j, d0, i0, d1, i1, d2v, i2);
                    }
                }
            }
            xlo = nxlo; xhi = nxhi; ylo = nylo; yhi = nyhi; zlo = nzlo; zhi = nzhi;
            havePrev = true;

            // termination: distance from c to nearest UNSCANNED slab
            float bound = INF;
            if (xlo > 0) bound = fminf(bound, cx - (float)xlo*HCELL);
            if (xhi < 7) bound = fminf(bound, (float)(xhi+1)*HCELL - cx);
            if (ylo > 0) bound = fminf(bound, cy - (float)ylo*HCELL);
            if (yhi < 7) bound = fminf(bound, (float)(yhi+1)*HCELL - cy);
            if (zlo > 0) bound = fminf(bound, cz - (float)zlo*HCELL);
            if (zhi < 7) bound = fminf(bound, (float)(zhi+1)*HCELL - cz);
            if (bound == INF) break;          // whole grid scanned
            bound -= 1e-3f;                   // fp cell-assignment margin
            if (bound > 0.0f) {
                float b2 = bound * bound;
                unsigned cnt = (unsigned)(d0 < b2) + (unsigned)(d1 < b2)
                             + (unsigned)(d2v < b2);
                if (__reduce_add_sync(gmask, cnt) >= 3) break;
            }
        }
    }

    // ONE merge of per-lane triples -> global top-3 (group-local mask)
    float td0 = d0, td1 = d1, td2 = d2v;
    int   ti0 = i0, ti1 = i1, ti2 = i2;
    #pragma unroll
    for (int s = 1; s < 16; s <<= 1) {
        float e0 = __shfl_xor_sync(gmask, td0, s);
        int   j0 = __shfl_xor_sync(gmask, ti0, s);
        float e1 = __shfl_xor_sync(gmask, td1, s);
        int   j1 = __shfl_xor_sync(gmask, ti1, s);
        float e2 = __shfl_xor_sync(gmask, td2, s);
        int   j2 = __shfl_xor_sync(gmask, ti2, s);
        ins3(e0, j0, td0, ti0, td1, ti1, td2, ti2);
        ins3(e1, j1, td0, ti0, td1, ti1, td2, ti2);
        ins3(e2, j2, td0, ti0, td1, ti1, td2, ti2);
    }

    const bool empty = !(td0 < INF);
    float r0 = (td0 < INF) ? 1.0f/(td0 + 1e-8f) : 0.0f;
    float r1 = (td1 < INF) ? 1.0f/(td1 + 1e-8f) : 0.0f;
    float r2 = (td2 < INF) ? 1.0f/(td2 + 1e-8f) : 0.0f;
    float ssum = fmaxf(r0 + r1 + r2, 1e-8f);
    float w0 = r0/ssum, w1 = r1/ssum, w2 = r2/ssum;
    if (ti0 < 0) ti0 = 0;
    if (ti1 < 0) ti1 = ti0;
    if (ti2 < 0) ti2 = ti0;

    // interp: lane handles 2 feature channels (float2) -> stage to smem
    {
        const float2* F0 = (const float2*)(g_feats + (b*NN + ti0)*32);
        const float2* F1 = (const float2*)(g_feats + (b*NN + ti1)*32);
        const float2* F2 = (const float2*)(g_feats + (b*NN + ti2)*32);
        float2 a = __ldg(&F0[l]), u = __ldg(&F1[l]), v = __ldg(&F2[l]);
        float2 f;
        f.x = empty ? 0.0f : (w0*a.x + w1*u.x + w2*v.x);
        f.y = empty ? 0.0f : (w0*a.y + w1*u.y + w2*v.y);
        ((float2*)sv[grp])[l] = f;
        if (l < 3) {
            int isel = (l == 0) ? ti0 : ((l == 1) ? ti1 : ti2);
            float4 p = __ldg(&pts[isel]);
            sv[grp][32 + l*3 + 0] = empty ? 0.0f : (cx - p.x);
            sv[grp][32 + l*3 + 1] = empty ? 0.0f : (cy - p.y);
            sv[grp][32 + l*3 + 2] = empty ? 0.0f : (cz - p.z);
        }
    }
    __syncwarp();

    // fused grouped conv: lane computes output channels 2l, 2l+1
    const float* wrow = g_wT + g*(41*CAGG) + 2*l;
    float a0 = 0.0f, a1 = 0.0f;
    #pragma unroll
    for (int i = 0; i < 41; ++i) {
        float vi = sv[grp][i];
        float2 w = *(const float2*)(wrow + i*CAGG);
        a0 = fmaf(vi, w.x, a0);
        a1 = fmaf(vi, w.y, a1);
    }
    const int gc = g*CAGG + 2*l;
    float2 r;
    r.x = fmaxf(fmaf(a0, __ldg(&g_sc1[gc]),   __ldg(&g_sh1[gc])),   0.0f);
    r.y = fmaxf(fmaf(a1, __ldg(&g_sc1[gc+1]), __ldg(&g_sh1[gc+1])), 0.0f);
    *(float2*)(g_x + m*GC + gc) = r;
}

// ---------------------------------------------------------------------------
// K_post: split-K GEMM partials. CTA tile 64m x 128n, k=96 per split.
// ---------------------------------------------------------------------------
__global__ __launch_bounds__(128) void k_post(const float* __restrict__ wp) {
    __shared__ float sA[32][68];
    __shared__ float sB[32][132];
    const int tid = threadIdx.x;
    const int tx = tid & 15;
    const int ty = tid >> 4;
    const int m0 = blockIdx.x * 64;
    const int kb0 = blockIdx.y * 96;

    float acc[8][8];
    #pragma unroll
    for (int i = 0; i < 8; ++i)
        #pragma unroll
        for (int j = 0; j < 8; ++j) acc[i][j] = 0.0f;

    for (int kc = 0; kc < 96; kc += 32) {
        const int kb = kb0 + kc;
        #pragma unroll
        for (int i = 0; i < 4; ++i) {               // A: 64m x 32k
            int f = tid + i*128;
            int mm = f >> 3, kq = (f & 7) << 2;
            float4 vv = *(const float4*)(g_x + (m0+mm)*GC + kb + kq);
            sA[kq+0][mm] = vv.x; sA[kq+1][mm] = vv.y;
            sA[kq+2][mm] = vv.z; sA[kq+3][mm] = vv.w;
        }
        #pragma unroll
        for (int i = 0; i < 8; ++i) {               // B: 128n x 32k
            int f = tid + i*128;
            int nr = f >> 3, kq = (f & 7) << 2;
            float4 vv = *(const float4*)(wp + nr*GC + kb + kq);
            sB[kq+0][nr] = vv.x; sB[kq+1][nr] = vv.y;
            sB[kq+2][nr] = vv.z; sB[kq+3][nr] = vv.w;
        }
        __syncthreads();
        #pragma unroll
        for (int k = 0; k < 32; ++k) {
            float av[8], bv[8];
            *(float4*)&av[0] = *(const float4*)&sA[k][ty*8];
            *(float4*)&av[4] = *(const float4*)&sA[k][ty*8 + 4];
            *(float4*)&bv[0] = *(const float4*)&sB[k][tx*4];
            *(float4*)&bv[4] = *(const float4*)&sB[k][64 + tx*4];
            #pragma unroll
            for (int i = 0; i < 8; ++i)
                #pragma unroll
                for (int j = 0; j < 8; ++j)
                    acc[i][j] = fmaf(av[i], bv[j], acc[i][j]);
        }
        __syncthreads();
    }

    float* dst = g_part[blockIdx.y];
    #pragma unroll
    for (int i = 0; i < 8; ++i) {
        int mrow = m0 + ty*8 + i;
        *(float4*)(dst + mrow*CPOST + tx*4)      = *(float4*)&acc[i][0];
        *(float4*)(dst + mrow*CPOST + 64 + tx*4) = *(float4*)&acc[i][4];
    }
}

// ---------------------------------------------------------------------------
// K_fin: sum split-K partials + BN2 + ReLU
// ---------------------------------------------------------------------------
__global__ void k_fin(const float* __restrict__ g2, const float* __restrict__ b2,
                      const float* __restrict__ mu2, const float* __restrict__ v2,
                      float* __restrict__ out) {
    int t = blockIdx.x * 256 + threadIdx.x;
    if (t >= BM*CPOST) return;
    int c = t & 127;
    float s = 0.0f;
    #pragma unroll
    for (int k = 0; k < KSPLIT; ++k) s += g_part[k][t];
    float scale = g2[c] * rsqrtf(v2[c] + 1e-5f);
    float shift = b2[c] - mu2[c]*scale;
    out[t] = fmaxf(fmaf(s, scale, shift), 0.0f);
}

// ---------------------------------------------------------------------------
extern "C" void kernel_launch(void* const* d_in, const int* in_sizes, int n_in,
                              void* d_out, int out_size) {
    const float* sxyz  = (const float*)d_in[0];
    const float* sfeat = (const float*)d_in[1];
    const float* nxyz  = (const float*)d_in[2];
    const float* wg    = (const float*)d_in[3];
    const float* g1    = (const float*)d_in[4];
    const float* b1    = (const float*)d_in[5];
    const float* m1    = (const float*)d_in[6];
    const float* v1    = (const float*)d_in[7];
    const float* wp    = (const float*)d_in[8];
    const float* g2    = (const float*)d_in[9];
    const float* b2    = (const float*)d_in[10];
    const float* m2    = (const float*)d_in[11];
    const float* v2    = (const float*)d_in[12];
    float* out = (float*)d_out;

    k_wt<<<(GG*41*CAGG + 255)/256, 256>>>(wg, g1, b1, m1, v1);
    k_bin<<<BB, 256>>>(sxyz);
    k_reduce<<<(BB*NN*32 + 255)/256, 256>>>(sfeat);
    k_nn<<<NCENT/16, 256>>>(nxyz);
    k_post<<<dim3(BM/64, KSPLIT), 128>>>(wp);
    k_fin<<<(BM*CPOST + 255)/256, 256>>>(g2, b2, m2, v2, out);
}